// round 6
// baseline (speedup 1.0000x reference)
#include <cuda_runtime.h>
#include <cuda_bf16.h>
#include <cstdint>
#include <cstddef>

#define B_SZ 2
#define QL   1024
#define ML   1024
#define KL   2048
#define DM   1024
#define NH   16
#define DH   64

// ============================ helpers =====================================
__device__ __forceinline__ uint32_t smem_u32(const void* p){
    uint32_t a;
    asm("{ .reg .u64 t; cvta.to.shared.u64 t, %1; cvt.u32.u64 %0, t; }" : "=r"(a) : "l"(p));
    return a;
}

#define SWZ(o) ((o) ^ (((o) >> 3) & 0x70))

__device__ __forceinline__ void ldsm_x4(uint32_t& r0, uint32_t& r1, uint32_t& r2,
                                        uint32_t& r3, uint32_t a){
    asm volatile("ldmatrix.sync.aligned.m8n8.x4.shared.b16 {%0,%1,%2,%3},[%4];"
                 : "=r"(r0), "=r"(r1), "=r"(r2), "=r"(r3) : "r"(a));
}
__device__ __forceinline__ void ldsm_x2(uint32_t& r0, uint32_t& r1, uint32_t a){
    asm volatile("ldmatrix.sync.aligned.m8n8.x2.shared.b16 {%0,%1},[%2];"
                 : "=r"(r0), "=r"(r1) : "r"(a));
}
__device__ __forceinline__ void mma16816(float* c, const uint32_t* a, const uint32_t* b){
    asm volatile(
        "mma.sync.aligned.m16n8k16.row.col.f32.bf16.bf16.f32 "
        "{%0,%1,%2,%3},{%4,%5,%6,%7},{%8,%9},{%0,%1,%2,%3};"
        : "+f"(c[0]), "+f"(c[1]), "+f"(c[2]), "+f"(c[3])
        : "r"(a[0]), "r"(a[1]), "r"(a[2]), "r"(a[3]), "r"(b[0]), "r"(b[1]));
}
__device__ __forceinline__ void cp16(uint32_t dst, const void* src){
    asm volatile("cp.async.cg.shared.global [%0], [%1], 16;" :: "r"(dst), "l"(src));
}
#define CP_COMMIT() asm volatile("cp.async.commit_group;" ::: "memory")
#define CP_WAIT0()  asm volatile("cp.async.wait_group 0;" ::: "memory")

__device__ __forceinline__ void pksplit(float a, float b, uint32_t& hi, uint32_t& lo){
    __nv_bfloat16 ha = __float2bfloat16(a), hb = __float2bfloat16(b);
    __nv_bfloat16 la = __float2bfloat16(a - __bfloat162float(ha));
    __nv_bfloat16 lb = __float2bfloat16(b - __bfloat162float(hb));
    __nv_bfloat162 H = __halves2bfloat162(ha, hb);
    __nv_bfloat162 L = __halves2bfloat162(la, lb);
    hi = *reinterpret_cast<uint32_t*>(&H);
    lo = *reinterpret_cast<uint32_t*>(&L);
}

// ============================ scratch pools ===============================
#define SZ_1M ((size_t)1024 * 1024)
#define SZ_2M ((size_t)2048 * 1024)
#define SZ_4M ((size_t)4096 * 1024)
#define SZ_P  ((size_t)B_SZ * NH * QL * KL)

constexpr size_t oHSPh = 0,               oHSPl = oHSPh + SZ_2M;
constexpr size_t oMSPh = oHSPl + SZ_2M,   oMSPl = oMSPh + SZ_2M;
constexpr size_t oRSPh = oMSPl + SZ_2M,   oRSPl = oRSPh + SZ_2M;
constexpr size_t oWT   = oRSPl + SZ_2M;                       // 5 x (hi 1M | lo 1M)
constexpr size_t oQWh  = oWT + 10 * SZ_1M, oQWl = oQWh + SZ_2M;
constexpr size_t oQRh  = oQWl + SZ_2M,    oQRl = oQRh + SZ_2M;
constexpr size_t oKh   = oQRl + SZ_2M,    oKl  = oKh + SZ_4M;
constexpr size_t oRHh  = oKl + SZ_4M,     oRHl = oRHh + SZ_2M;
constexpr size_t oVTh  = oRHl + SZ_2M,    oVTl = oVTh + SZ_4M;
constexpr size_t oAVh  = oVTl + SZ_4M,    oAVl = oAVh + SZ_2M;
constexpr size_t BF_TOTAL = oAVl + SZ_2M;

constexpr size_t fQ  = 0;
constexpr size_t fK  = fQ + SZ_2M;
constexpr size_t fV  = fK + SZ_4M;
constexpr size_t fR  = fV + SZ_4M;
constexpr size_t fAV = fR + SZ_2M;
constexpr size_t fBD = fAV + SZ_2M;
constexpr size_t F_TOTAL = fBD + SZ_P;

__device__ __nv_bfloat16 g_bf[BF_TOTAL];
__device__ float         g_f [F_TOTAL];

// ============================ GEMM core (mma.sync) ========================
template <int NT>
__device__ __forceinline__ void gemm_core(
    const __nv_bfloat16* __restrict__ Ahi, const __nv_bfloat16* __restrict__ Alo, int lda,
    const __nv_bfloat16* __restrict__ Bhi, const __nv_bfloat16* __restrict__ Blo, int ldb,
    float* __restrict__ C, int ldc, int K)
{
    __shared__ __align__(1024) uint8_t sA[128 * 128];
    __shared__ __align__(1024) uint8_t sB[NT * 128];

    const int tid  = threadIdx.x;
    const int wid  = tid >> 5;
    const int lane = tid & 31;
    const int wm   = wid & 3;
    const int wn   = wid >> 2;
    constexpr int WN     = NT / 2;
    constexpr int NTILES = WN / 8;
    constexpr int BSEG   = NT / 32;

    const uint32_t a32 = smem_u32(sA), b32 = smem_u32(sB);

    float acc[2][NTILES][4];
#pragma unroll
    for (int mt = 0; mt < 2; mt++)
#pragma unroll
        for (int nt = 0; nt < NTILES; nt++)
#pragma unroll
            for (int q = 0; q < 4; q++) acc[mt][nt][q] = 0.0f;

    uint4 pa[4], pb[BSEG];
    const int nch = K >> 5;

    auto ldg_chunk = [&](int k0){
#pragma unroll
        for (int i = 0; i < 4; i++){
            int s = tid + (i << 8); int row = s >> 3, j = s & 7;
            const __nv_bfloat16* p = (j < 4)
                ? Ahi + (size_t)row * lda + k0 + j * 8
                : Alo + (size_t)row * lda + k0 + (j - 4) * 8;
            pa[i] = *reinterpret_cast<const uint4*>(p);
        }
#pragma unroll
        for (int i = 0; i < BSEG; i++){
            int s = tid + (i << 8); int row = s >> 3, j = s & 7;
            const __nv_bfloat16* p = (j < 4)
                ? Bhi + (size_t)row * ldb + k0 + j * 8
                : Blo + (size_t)row * ldb + k0 + (j - 4) * 8;
            pb[i] = *reinterpret_cast<const uint4*>(p);
        }
    };

    const uint32_t aRowOff0 = (uint32_t)((wm * 32 + (lane & 15)) << 7) + ((lane >> 4) << 4);
    const uint32_t bRowOff  = (uint32_t)((wn * WN + (lane & 7)) << 7) + (((lane >> 3) & 1) << 4);

    ldg_chunk(0);

    for (int c = 0; c < nch; c++){
#pragma unroll
        for (int i = 0; i < 4; i++){
            int s = tid + (i << 8);
            uint32_t off = (uint32_t)((s >> 3) << 7) + (uint32_t)((s & 7) << 4);
            *reinterpret_cast<uint4*>(sA + SWZ(off)) = pa[i];
        }
#pragma unroll
        for (int i = 0; i < BSEG; i++){
            int s = tid + (i << 8);
            uint32_t off = (uint32_t)((s >> 3) << 7) + (uint32_t)((s & 7) << 4);
            *reinterpret_cast<uint4*>(sB + SWZ(off)) = pb[i];
        }
        __syncthreads();

        if (c + 1 < nch) ldg_chunk((c + 1) << 5);

#pragma unroll
        for (int kh = 0; kh < 2; kh++){
            const uint32_t hiOff = (uint32_t)(kh << 5);
            const uint32_t loOff = hiOff + 64;

            uint32_t ah[2][4], al[2][4];
#pragma unroll
            for (int mt = 0; mt < 2; mt++){
                uint32_t base = aRowOff0 + (uint32_t)(mt << 11);
                ldsm_x4(ah[mt][0], ah[mt][1], ah[mt][2], ah[mt][3],
                        a32 + SWZ(base + hiOff));
                ldsm_x4(al[mt][0], al[mt][1], al[mt][2], al[mt][3],
                        a32 + SWZ(base + loOff));
            }
#pragma unroll
            for (int nt = 0; nt < NTILES; nt++){
                uint32_t b[2];
                ldsm_x2(b[0], b[1], b32 + SWZ(bRowOff + (uint32_t)(nt << 10) + hiOff));
                mma16816(acc[0][nt], ah[0], b);
                mma16816(acc[1][nt], ah[1], b);
                mma16816(acc[0][nt], al[0], b);
                mma16816(acc[1][nt], al[1], b);
            }
#pragma unroll
            for (int nt = 0; nt < NTILES; nt++){
                uint32_t b[2];
                ldsm_x2(b[0], b[1], b32 + SWZ(bRowOff + (uint32_t)(nt << 10) + loOff));
                mma16816(acc[0][nt], ah[0], b);
                mma16816(acc[1][nt], ah[1], b);
            }
        }
        __syncthreads();
    }

    const int r0 = wm * 32 + (lane >> 2);
    const int cc = (lane & 3) * 2;
#pragma unroll
    for (int mt = 0; mt < 2; mt++){
#pragma unroll
        for (int nt = 0; nt < NTILES; nt++){
            const int col = wn * WN + nt * 8 + cc;
            float* p0 = C + (size_t)(r0 + mt * 16) * ldc + col;
            float* p1 = C + (size_t)(r0 + mt * 16 + 8) * ldc + col;
            *reinterpret_cast<float2*>(p0) = make_float2(acc[mt][nt][0], acc[mt][nt][1]);
            *reinterpret_cast<float2*>(p1) = make_float2(acc[mt][nt][2], acc[mt][nt][3]);
        }
    }
}

// ============================ GEMM wrappers ===============================
__global__ __launch_bounds__(256)
void k_proj(const __nv_bfloat16* __restrict__ Ah, const __nv_bfloat16* __restrict__ Al,
            const __nv_bfloat16* __restrict__ Bh, const __nv_bfloat16* __restrict__ Bl,
            float* __restrict__ C)
{
    size_t ao = (size_t)blockIdx.y * 128 * DM;
    size_t bo = (size_t)blockIdx.x * 128 * DM;
    float* Cp = C + (size_t)blockIdx.y * 128 * DM + blockIdx.x * 128;
    gemm_core<128>(Ah + ao, Al + ao, DM, Bh + bo, Bl + bo, DM, Cp, DM, DM);
}

__global__ __launch_bounds__(256)
void k_proj_cat(const __nv_bfloat16* __restrict__ Mh, const __nv_bfloat16* __restrict__ Ml,
                const __nv_bfloat16* __restrict__ Hh, const __nv_bfloat16* __restrict__ Hl,
                const __nv_bfloat16* __restrict__ Bh, const __nv_bfloat16* __restrict__ Bl,
                float* __restrict__ C)
{
    const int b = blockIdx.z, m0 = blockIdx.y * 128;
    const __nv_bfloat16 *Ah, *Al;
    if (m0 < ML){ size_t o = ((size_t)b * ML + m0) * DM; Ah = Mh + o; Al = Ml + o; }
    else        { size_t o = ((size_t)b * QL + (m0 - ML)) * DM; Ah = Hh + o; Al = Hl + o; }
    size_t bo = (size_t)blockIdx.x * 128 * DM;
    float* Cp = C + ((size_t)b * KL + m0) * DM + blockIdx.x * 128;
    gemm_core<128>(Ah, Al, DM, Bh + bo, Bl + bo, DM, Cp, DM, DM);
}

// bd score GEMM (q+rrb) . r_head^T -> raw BD matrix
__global__ __launch_bounds__(256)
void k_score(const __nv_bfloat16* __restrict__ Qh, const __nv_bfloat16* __restrict__ Ql,
             const __nv_bfloat16* __restrict__ Kh, const __nv_bfloat16* __restrict__ Kl2,
             float* __restrict__ Sout)
{
    const int z = blockIdx.z, b = z >> 4, h = z & 15;
    const int i0 = blockIdx.y * 128, j0 = blockIdx.x * 128;
    size_t ao = ((size_t)(b * QL + i0)) * DM + h * DH;
    size_t bo = (size_t)j0 * DM + h * DH;
    float* Cp = Sout + ((size_t)z * QL + i0) * KL + j0;
    gemm_core<128>(Qh + ao, Ql + ao, DM, Kh + bo, Kl2 + bo, DM, Cp, KL, DH);
}

// ============================ flash attention =============================
// CTA: 64 q-rows x one (b,h). 128 threads = 4 warps x 16 rows.
// smem: Q (2 chunks x 64 x 128B) + double-buffered K (2 x 128 x 128B) and
// VT (4 x 64 x 128B) tiles. cp.async pipelined over 16 j-tiles of 128.
#define FL_QOFF   0
#define FL_KOFF   16384
#define FL_VOFF   49152
#define FL_BUFS   65536
#define FL_SMEM   147456

__global__ __launch_bounds__(128)
void k_flash(const __nv_bfloat16* __restrict__ Qh, const __nv_bfloat16* __restrict__ Ql,
             const __nv_bfloat16* __restrict__ Kh, const __nv_bfloat16* __restrict__ Kl,
             const __nv_bfloat16* __restrict__ VTh, const __nv_bfloat16* __restrict__ VTl,
             const float* __restrict__ BD, float* __restrict__ AV)
{
    extern __shared__ __align__(1024) uint8_t fsm[];
    const uint32_t smb = smem_u32(fsm);

    const int tid = threadIdx.x, lane = tid & 31, wid = tid >> 5;
    const int z = blockIdx.y, b = z >> 4, h = z & 15;
    const int i0 = blockIdx.x * 64;
    const int hoff = h * DH;
    const size_t bq = (size_t)b * KL;            // K row base
    const size_t bv = (size_t)b * DM + hoff;     // VT row base

    // ---- async tile loaders ----
    auto load_q = [&](){
#pragma unroll
        for (int i = 0; i < 8; i++){
            int s = tid + (i << 7);
            int c = s >> 9, row = (s >> 3) & 63, j = s & 7;
            const __nv_bfloat16* src = (j < 4)
                ? Qh + ((size_t)(b * QL + i0 + row)) * DM + hoff + c * 32 + j * 8
                : Ql + ((size_t)(b * QL + i0 + row)) * DM + hoff + c * 32 + (j - 4) * 8;
            cp16(smb + FL_QOFF + c * 8192 + SWZ((row << 7) + (j << 4)), src);
        }
    };
    auto load_tile = [&](int jt, int buf){
        const int j0 = jt * 128;
        const uint32_t kb = smb + FL_KOFF + buf * FL_BUFS;
        const uint32_t vb = smb + FL_VOFF + buf * FL_BUFS;
#pragma unroll
        for (int i = 0; i < 16; i++){
            int s = tid + (i << 7);
            int c = s >> 10, row = (s >> 3) & 127, j = s & 7;
            const __nv_bfloat16* src = (j < 4)
                ? Kh + (bq + j0 + row) * DM + hoff + c * 32 + j * 8
                : Kl + (bq + j0 + row) * DM + hoff + c * 32 + (j - 4) * 8;
            cp16(kb + c * 16384 + SWZ((row << 7) + (j << 4)), src);
        }
#pragma unroll
        for (int i = 0; i < 16; i++){
            int s = tid + (i << 7);
            int c = s >> 9, row = (s >> 3) & 63, j = s & 7;
            const __nv_bfloat16* src = (j < 4)
                ? VTh + (bv + row) * KL + j0 + c * 32 + j * 8
                : VTl + (bv + row) * KL + j0 + c * 32 + (j - 4) * 8;
            cp16(vb + c * 8192 + SWZ((row << 7) + (j << 4)), src);
        }
    };

    load_q();
    load_tile(0, 0);
    CP_COMMIT();
    CP_WAIT0();
    __syncthreads();

    // ---- Q fragments (persist across j-loop) ----
    uint32_t qh4[4][4], ql4[4][4];
    {
        const uint32_t arow = (uint32_t)(((wid << 4) + (lane & 15)) << 7) + ((lane >> 4) << 4);
#pragma unroll
        for (int c = 0; c < 2; c++)
#pragma unroll
            for (int kh = 0; kh < 2; kh++){
                const int ki = c * 2 + kh;
                ldsm_x4(qh4[ki][0], qh4[ki][1], qh4[ki][2], qh4[ki][3],
                        smb + FL_QOFF + c * 8192 + SWZ(arow + (kh << 5)));
                ldsm_x4(ql4[ki][0], ql4[ki][1], ql4[ki][2], ql4[ki][3],
                        smb + FL_QOFF + c * 8192 + SWZ(arow + (kh << 5) + 64));
            }
    }

    float acc_o[8][4];
#pragma unroll
    for (int n = 0; n < 8; n++)
#pragma unroll
        for (int q = 0; q < 4; q++) acc_o[n][q] = 0.0f;
    float l0 = 0.0f, l1 = 0.0f, mr0 = -1e30f, mr1 = -1e30f;

    const int ig0 = i0 + (wid << 4) + (lane >> 2);
    const int ig1 = ig0 + 8;
    const float* x00 = BD + ((size_t)z * QL + ig0) * KL;
    const float* x01 = BD + ((size_t)z * QL + ig1) * KL;

    const uint32_t bro = (uint32_t)((lane & 7) << 7) + (((lane >> 3) & 1) << 4);

    for (int jt = 0; jt < 16; jt++){
        const int buf = jt & 1;
        const int j0 = jt * 128;
        if (jt + 1 < 16) load_tile(jt + 1, buf ^ 1);
        CP_COMMIT();

        const uint32_t kb = smb + FL_KOFF + buf * FL_BUFS;
        const uint32_t vb = smb + FL_VOFF + buf * FL_BUFS;

        // ---- S = QW . K^T (3 combos, fp32 acc) ----
        float acc_s[16][4];
#pragma unroll
        for (int n = 0; n < 16; n++)
#pragma unroll
            for (int q = 0; q < 4; q++) acc_s[n][q] = 0.0f;

#pragma unroll
        for (int ki = 0; ki < 4; ki++){
            const uint32_t cb = kb + (uint32_t)((ki >> 1) * 16384);
            const uint32_t ho = (uint32_t)((ki & 1) << 5);
#pragma unroll
            for (int nt = 0; nt < 16; nt++){
                uint32_t bb[2];
                ldsm_x2(bb[0], bb[1], cb + SWZ(bro + (uint32_t)(nt << 10) + ho));
                mma16816(acc_s[nt], qh4[ki], bb);
                mma16816(acc_s[nt], ql4[ki], bb);
                uint32_t bl[2];
                ldsm_x2(bl[0], bl[1], cb + SWZ(bro + (uint32_t)(nt << 10) + ho + 64));
                mma16816(acc_s[nt], qh4[ki], bl);
            }
        }

        // ---- bd gather + scale + online softmax ----
        float tm0 = -1e30f, tm1 = -1e30f;
#pragma unroll
        for (int nt = 0; nt < 16; nt++){
#pragma unroll
            for (int e = 0; e < 2; e++){
                const int j = j0 + (nt << 3) + ((lane & 3) << 1) + e;
                const int d0 = j - ig0;
                float bd0 = (d0 <= QL) ? x00[d0 + (QL - 1)]
                          : (d0 == QL + 1) ? 0.0f : x00[KL + d0 - (QL + 2)];
                float s0 = (acc_s[nt][e] + bd0) * 0.125f;
                acc_s[nt][e] = s0; tm0 = fmaxf(tm0, s0);
                const int d1 = j - ig1;
                float bd1 = (d1 <= QL) ? x01[d1 + (QL - 1)]
                          : (d1 == QL + 1) ? 0.0f : x01[KL + d1 - (QL + 2)];
                float s1 = (acc_s[nt][2 + e] + bd1) * 0.125f;
                acc_s[nt][2 + e] = s1; tm1 = fmaxf(tm1, s1);
            }
        }
        tm0 = fmaxf(tm0, __shfl_xor_sync(0xffffffffu, tm0, 1));
        tm0 = fmaxf(tm0, __shfl_xor_sync(0xffffffffu, tm0, 2));
        tm1 = fmaxf(tm1, __shfl_xor_sync(0xffffffffu, tm1, 1));
        tm1 = fmaxf(tm1, __shfl_xor_sync(0xffffffffu, tm1, 2));

        const float nm0 = fmaxf(mr0, tm0), nm1 = fmaxf(mr1, tm1);
        const float sc0 = __expf(mr0 - nm0), sc1 = __expf(mr1 - nm1);
        mr0 = nm0; mr1 = nm1;

        float sum0 = 0.0f, sum1 = 0.0f;
#pragma unroll
        for (int nt = 0; nt < 16; nt++){
#pragma unroll
            for (int e = 0; e < 2; e++){
                float p0 = __expf(acc_s[nt][e] - nm0);
                acc_s[nt][e] = p0; sum0 += p0;
                float p1 = __expf(acc_s[nt][2 + e] - nm1);
                acc_s[nt][2 + e] = p1; sum1 += p1;
            }
        }
        sum0 += __shfl_xor_sync(0xffffffffu, sum0, 1);
        sum0 += __shfl_xor_sync(0xffffffffu, sum0, 2);
        sum1 += __shfl_xor_sync(0xffffffffu, sum1, 1);
        sum1 += __shfl_xor_sync(0xffffffffu, sum1, 2);
        l0 = l0 * sc0 + sum0;
        l1 = l1 * sc1 + sum1;
#pragma unroll
        for (int n = 0; n < 8; n++){
            acc_o[n][0] *= sc0; acc_o[n][1] *= sc0;
            acc_o[n][2] *= sc1; acc_o[n][3] *= sc1;
        }

        // ---- O += P . V  (P split hi/lo, V split: 3 combos) ----
#pragma unroll
        for (int t = 0; t < 8; t++){
            uint32_t aph[4], apl[4];
            pksplit(acc_s[2 * t][0],     acc_s[2 * t][1],     aph[0], apl[0]);
            pksplit(acc_s[2 * t][2],     acc_s[2 * t][3],     aph[1], apl[1]);
            pksplit(acc_s[2 * t + 1][0], acc_s[2 * t + 1][1], aph[2], apl[2]);
            pksplit(acc_s[2 * t + 1][2], acc_s[2 * t + 1][3], aph[3], apl[3]);

            const uint32_t cb = vb + (uint32_t)((t >> 1) * 8192);
            const uint32_t ho = (uint32_t)((t & 1) << 5);
#pragma unroll
            for (int n = 0; n < 8; n++){
                uint32_t bh[2];
                ldsm_x2(bh[0], bh[1], cb + SWZ(bro + (uint32_t)(n << 10) + ho));
                mma16816(acc_o[n], aph, bh);
                mma16816(acc_o[n], apl, bh);
                uint32_t bl[2];
                ldsm_x2(bl[0], bl[1], cb + SWZ(bro + (uint32_t)(n << 10) + ho + 64));
                mma16816(acc_o[n], aph, bl);
            }
        }

        CP_WAIT0();
        __syncthreads();
    }

    // ---- epilogue: normalize and store attn_vec ----
    const float iv0 = 1.0f / l0, iv1 = 1.0f / l1;
    const int col = (lane & 3) << 1;
    float* o0 = AV + ((size_t)(b * QL + ig0)) * DM + hoff;
    float* o1 = AV + ((size_t)(b * QL + ig1)) * DM + hoff;
#pragma unroll
    for (int n = 0; n < 8; n++){
        *reinterpret_cast<float2*>(o0 + n * 8 + col) =
            make_float2(acc_o[n][0] * iv0, acc_o[n][1] * iv0);
        *reinterpret_cast<float2*>(o1 + n * 8 + col) =
            make_float2(acc_o[n][2] * iv1, acc_o[n][3] * iv1);
    }
}

// ============================ conversions =================================
__device__ __forceinline__ void split1(float x, __nv_bfloat16& h, __nv_bfloat16& l){
    h = __float2bfloat16(x);
    l = __float2bfloat16(x - __bfloat162float(h));
}

__global__ __launch_bounds__(256)
void k_split(const float* __restrict__ x, __nv_bfloat16* __restrict__ h,
             __nv_bfloat16* __restrict__ l, size_t n)
{
    size_t i = ((size_t)blockIdx.x * 256 + threadIdx.x) * 4;
    if (i >= n) return;
    float4 v = *reinterpret_cast<const float4*>(x + i);
    __nv_bfloat16 h0, h1, h2, h3, l0, l1, l2, l3;
    split1(v.x, h0, l0); split1(v.y, h1, l1);
    split1(v.z, h2, l2); split1(v.w, h3, l3);
    *reinterpret_cast<__nv_bfloat162*>(h + i)     = __halves2bfloat162(h0, h1);
    *reinterpret_cast<__nv_bfloat162*>(h + i + 2) = __halves2bfloat162(h2, h3);
    *reinterpret_cast<__nv_bfloat162*>(l + i)     = __halves2bfloat162(l0, l1);
    *reinterpret_cast<__nv_bfloat162*>(l + i + 2) = __halves2bfloat162(l2, l3);
}

__global__ __launch_bounds__(256)
void k_split_qbias(const float* __restrict__ q,
                   const float* __restrict__ b1, const float* __restrict__ b2,
                   __nv_bfloat16* __restrict__ h1, __nv_bfloat16* __restrict__ l1,
                   __nv_bfloat16* __restrict__ h2, __nv_bfloat16* __restrict__ l2,
                   size_t n)
{
    size_t i = ((size_t)blockIdx.x * 256 + threadIdx.x) * 4;
    if (i >= n) return;
    const int col = (int)(i & (DM - 1));
    float4 v = *reinterpret_cast<const float4*>(q + i);
    float4 a = *reinterpret_cast<const float4*>(b1 + col);
    float4 c = *reinterpret_cast<const float4*>(b2 + col);
    __nv_bfloat16 h0, h1b, h2b, h3, l0, l1b, l2b, l3;
    split1(v.x + a.x, h0, l0);  split1(v.y + a.y, h1b, l1b);
    split1(v.z + a.z, h2b, l2b); split1(v.w + a.w, h3, l3);
    *reinterpret_cast<__nv_bfloat162*>(h1 + i)     = __halves2bfloat162(h0, h1b);
    *reinterpret_cast<__nv_bfloat162*>(h1 + i + 2) = __halves2bfloat162(h2b, h3);
    *reinterpret_cast<__nv_bfloat162*>(l1 + i)     = __halves2bfloat162(l0, l1b);
    *reinterpret_cast<__nv_bfloat162*>(l1 + i + 2) = __halves2bfloat162(l2b, l3);
    split1(v.x + c.x, h0, l0);  split1(v.y + c.y, h1b, l1b);
    split1(v.z + c.z, h2b, l2b); split1(v.w + c.w, h3, l3);
    *reinterpret_cast<__nv_bfloat162*>(h2 + i)     = __halves2bfloat162(h0, h1b);
    *reinterpret_cast<__nv_bfloat162*>(h2 + i + 2) = __halves2bfloat162(h2b, h3);
    *reinterpret_cast<__nv_bfloat162*>(l2 + i)     = __halves2bfloat162(l0, l1b);
    *reinterpret_cast<__nv_bfloat162*>(l2 + i + 2) = __halves2bfloat162(l2b, l3);
}

// out[b][c][r] = split(x[b][r][c]) ; grid (C/32, R/32, batch), block (32,8)
__global__ __launch_bounds__(256)
void k_tsplit(const float* __restrict__ x, __nv_bfloat16* __restrict__ th,
              __nv_bfloat16* __restrict__ tl, int R, int C)
{
    __shared__ float t[32][33];
    const int bz = blockIdx.z;
    const float* xb = x + (size_t)bz * R * C;
    __nv_bfloat16* ph = th + (size_t)bz * R * C;
    __nv_bfloat16* pl = tl + (size_t)bz * R * C;
    const int c0 = blockIdx.x * 32, r0 = blockIdx.y * 32;
    const int tx = threadIdx.x, ty = threadIdx.y;
    for (int i = ty; i < 32; i += 8)
        t[i][tx] = xb[(size_t)(r0 + i) * C + c0 + tx];
    __syncthreads();
    for (int i = ty; i < 32; i += 8){
        __nv_bfloat16 h, l; split1(t[tx][i], h, l);
        ph[(size_t)(c0 + i) * R + r0 + tx] = h;
        pl[(size_t)(c0 + i) * R + r0 + tx] = l;
    }
}

// ============================ launch ======================================
extern "C" void kernel_launch(void* const* d_in, const int* in_sizes, int n_in,
                              void* d_out, int out_size)
{
    const float* h_in  = (const float*)d_in[0];
    const float* mem_p = (const float*)d_in[1];
    const float* r_p   = (const float*)d_in[2];
    const float* W[5]  = { (const float*)d_in[3], (const float*)d_in[4],
                           (const float*)d_in[5], (const float*)d_in[6],
                           (const float*)d_in[7] };   // Wq, Wk, Wv, Wr, Wo
    const float* rwb   = (const float*)d_in[8];
    const float* rrb   = (const float*)d_in[9];
    float* out = (float*)d_out;

    __nv_bfloat16* bf; float* fp;
    cudaGetSymbolAddress((void**)&bf, g_bf);
    cudaGetSymbolAddress((void**)&fp, g_f);

    cudaFuncSetAttribute(k_flash, cudaFuncAttributeMaxDynamicSharedMemorySize, FL_SMEM);

    // 1) split inputs
    k_split<<<2048, 256>>>(h_in,  bf + oHSPh, bf + oHSPl, SZ_2M);
    k_split<<<2048, 256>>>(mem_p, bf + oMSPh, bf + oMSPl, SZ_2M);
    k_split<<<2048, 256>>>(r_p,   bf + oRSPh, bf + oRSPl, SZ_2M);

    // 2) transpose+split weights: Wt[n][k]
    for (int w = 0; w < 5; w++){
        __nv_bfloat16* th = bf + oWT + (size_t)w * 2 * SZ_1M;
        k_tsplit<<<dim3(32, 32, 1), dim3(32, 8)>>>(W[w], th, th + SZ_1M, 1024, 1024);
    }
    const __nv_bfloat16 *wq = bf + oWT,            *wk = bf + oWT + 2 * SZ_1M,
                        *wv = bf + oWT + 4 * SZ_1M, *wr = bf + oWT + 6 * SZ_1M,
                        *wo = bf + oWT + 8 * SZ_1M;

    // 3) projections (mma.sync)
    k_proj<<<dim3(8, 16), 256>>>(bf + oHSPh, bf + oHSPl, wq, wq + SZ_1M, fp + fQ);
    k_proj_cat<<<dim3(8, 16, 2), 256>>>(bf + oMSPh, bf + oMSPl, bf + oHSPh, bf + oHSPl,
                                        wk, wk + SZ_1M, fp + fK);
    k_proj_cat<<<dim3(8, 16, 2), 256>>>(bf + oMSPh, bf + oMSPl, bf + oHSPh, bf + oHSPl,
                                        wv, wv + SZ_1M, fp + fV);
    k_proj<<<dim3(8, 16), 256>>>(bf + oRSPh, bf + oRSPl, wr, wr + SZ_1M, fp + fR);

    // 4) split projections
    k_split_qbias<<<2048, 256>>>(fp + fQ, rwb, rrb,
                                 bf + oQWh, bf + oQWl, bf + oQRh, bf + oQRl, SZ_2M);
    k_split<<<4096, 256>>>(fp + fK, bf + oKh,  bf + oKl,  SZ_4M);
    k_split<<<2048, 256>>>(fp + fR, bf + oRHh, bf + oRHl, SZ_2M);
    k_tsplit<<<dim3(32, 64, 2), dim3(32, 8)>>>(fp + fV, bf + oVTh, bf + oVTl, KL, DM);

    // 5) bd raw scores (fp32)
    k_score<<<dim3(16, 8, 32), 256>>>(bf + oQRh, bf + oQRl, bf + oRHh, bf + oRHl,
                                      fp + fBD);

    // 6) flash: ac + rel_shift(bd) + softmax + P.V fused
    k_flash<<<dim3(QL / 64, B_SZ * NH), 128, FL_SMEM>>>(
        bf + oQWh, bf + oQWl, bf + oKh, bf + oKl,
        bf + oVTh, bf + oVTl, fp + fBD, fp + fAV);

    // 7) out = attn_vec @ Wo
    k_split<<<2048, 256>>>(fp + fAV, bf + oAVh, bf + oAVl, SZ_2M);
    k_proj<<<dim3(8, 16), 256>>>(bf + oAVh, bf + oAVl, wo, wo + SZ_1M, out);
}

// round 7
// speedup vs baseline: 1.5403x; 1.5403x over previous
#include <cuda_runtime.h>
#include <cuda_bf16.h>
#include <cstdint>
#include <cstddef>

#define B_SZ 2
#define QL   1024
#define ML   1024
#define KL   2048
#define DM   1024
#define NH   16
#define DH   64

// ============================ helpers =====================================
__device__ __forceinline__ uint32_t smem_u32(const void* p){
    uint32_t a;
    asm("{ .reg .u64 t; cvta.to.shared.u64 t, %1; cvt.u32.u64 %0, t; }" : "=r"(a) : "l"(p));
    return a;
}

#define SWZ(o) ((o) ^ (((o) >> 3) & 0x70))

__device__ __forceinline__ void ldsm_x4(uint32_t& r0, uint32_t& r1, uint32_t& r2,
                                        uint32_t& r3, uint32_t a){
    asm volatile("ldmatrix.sync.aligned.m8n8.x4.shared.b16 {%0,%1,%2,%3},[%4];"
                 : "=r"(r0), "=r"(r1), "=r"(r2), "=r"(r3) : "r"(a));
}
__device__ __forceinline__ void mma16816(float* c, const uint32_t* a, const uint32_t* b){
    asm volatile(
        "mma.sync.aligned.m16n8k16.row.col.f32.bf16.bf16.f32 "
        "{%0,%1,%2,%3},{%4,%5,%6,%7},{%8,%9},{%0,%1,%2,%3};"
        : "+f"(c[0]), "+f"(c[1]), "+f"(c[2]), "+f"(c[3])
        : "r"(a[0]), "r"(a[1]), "r"(a[2]), "r"(a[3]), "r"(b[0]), "r"(b[1]));
}
__device__ __forceinline__ void cp16(uint32_t dst, const void* src){
    asm volatile("cp.async.cg.shared.global [%0], [%1], 16;" :: "r"(dst), "l"(src));
}
#define CP_COMMIT() asm volatile("cp.async.commit_group;" ::: "memory")
#define CP_WAIT0()  asm volatile("cp.async.wait_group 0;" ::: "memory")
#define CP_WAIT1()  asm volatile("cp.async.wait_group 1;" ::: "memory")

// ============================ scratch pools ===============================
#define SZ_1M ((size_t)1024 * 1024)
#define SZ_2M ((size_t)2048 * 1024)
#define SZ_4M ((size_t)4096 * 1024)
#define SZ_P  ((size_t)B_SZ * NH * QL * KL)

constexpr size_t oHSPh = 0,               oHSPl = oHSPh + SZ_2M;
constexpr size_t oMSPh = oHSPl + SZ_2M,   oMSPl = oMSPh + SZ_2M;
constexpr size_t oRSPh = oMSPl + SZ_2M,   oRSPl = oRSPh + SZ_2M;
constexpr size_t oWT   = oRSPl + SZ_2M;                       // 5 x (hi 1M | lo 1M)
constexpr size_t oQWh  = oWT + 10 * SZ_1M, oQWl = oQWh + SZ_2M;
constexpr size_t oQRh  = oQWl + SZ_2M,    oQRl = oQRh + SZ_2M;
constexpr size_t oKh   = oQRl + SZ_2M,    oKl  = oKh + SZ_4M;
constexpr size_t oRHh  = oKl + SZ_4M,     oRHl = oRHh + SZ_2M;
constexpr size_t oVTh  = oRHl + SZ_2M,    oVTl = oVTh + SZ_4M;
constexpr size_t oPh   = oVTl + SZ_4M,    oPl  = oPh + SZ_P;
constexpr size_t oAVh  = oPl + SZ_P,      oAVl = oAVh + SZ_2M;
constexpr size_t BF_TOTAL = oAVl + SZ_2M;

constexpr size_t fQ  = 0;
constexpr size_t fK  = fQ + SZ_2M;
constexpr size_t fV  = fK + SZ_4M;
constexpr size_t fR  = fV + SZ_4M;
constexpr size_t fAV = fR + SZ_2M;
constexpr size_t fS  = fAV + SZ_2M;
constexpr size_t fBD = fS + SZ_P;
constexpr size_t F_TOTAL = fBD + SZ_P;

__device__ __nv_bfloat16 g_bf[BF_TOTAL];
__device__ float         g_f [F_TOTAL];

// ============================ GEMM core (mma.sync) ========================
// C[128, NT] = (Ahi+Alo)[128,K] * (Bhi+Blo)[NT,K]^T, dropping lo*lo.
// smem rows are 128B: [32 hi bf16 | 32 lo bf16] per 32-element K chunk, SW128.
// cp.async double-buffered stages; 8 warps: wm = wid&3 (32 rows), wn = wid>>2.
template <int NT>
__device__ __forceinline__ void gemm_core(
    const __nv_bfloat16* __restrict__ Ahi, const __nv_bfloat16* __restrict__ Alo, int lda,
    const __nv_bfloat16* __restrict__ Bhi, const __nv_bfloat16* __restrict__ Blo, int ldb,
    float* __restrict__ C, int ldc, int K)
{
    extern __shared__ __align__(1024) uint8_t dynsm[];
    // layout: A stage0 16KB | A stage1 16KB | B stage0 NT*128 | B stage1 NT*128
    const uint32_t a32 = smem_u32(dynsm);
    const uint32_t b32 = a32 + 32768;
    constexpr uint32_t BSTRIDE = (uint32_t)NT * 128;

    const int tid  = threadIdx.x;
    const int wid  = tid >> 5;
    const int lane = tid & 31;
    const int wm   = wid & 3;
    const int wn   = wid >> 2;
    constexpr int WN     = NT / 2;
    constexpr int NTILES = WN / 8;
    constexpr int NPAIR  = NTILES / 2;
    constexpr int BSEG   = NT / 32;     // cp16 ops per thread for B stage

    float acc[2][NTILES][4];
#pragma unroll
    for (int mt = 0; mt < 2; mt++)
#pragma unroll
        for (int nt = 0; nt < NTILES; nt++)
#pragma unroll
            for (int q = 0; q < 4; q++) acc[mt][nt][q] = 0.0f;

    const int nch = K >> 5;

    auto load_stage = [&](int k0, int buf){
#pragma unroll
        for (int i = 0; i < 4; i++){
            int s = tid + (i << 8); int row = s >> 3, j = s & 7;
            const __nv_bfloat16* p = (j < 4)
                ? Ahi + (size_t)row * lda + k0 + j * 8
                : Alo + (size_t)row * lda + k0 + (j - 4) * 8;
            cp16(a32 + (uint32_t)buf * 16384u + SWZ((uint32_t)(row << 7) + (uint32_t)(j << 4)), p);
        }
#pragma unroll
        for (int i = 0; i < BSEG; i++){
            int s = tid + (i << 8); int row = s >> 3, j = s & 7;
            const __nv_bfloat16* p = (j < 4)
                ? Bhi + (size_t)row * ldb + k0 + j * 8
                : Blo + (size_t)row * ldb + k0 + (j - 4) * 8;
            cp16(b32 + (uint32_t)buf * BSTRIDE + SWZ((uint32_t)(row << 7) + (uint32_t)(j << 4)), p);
        }
    };

    // fragment lane addressing
    const uint32_t aRowOff0 = (uint32_t)((wm * 32 + (lane & 15)) << 7) + ((lane >> 4) << 4);
    // x4 B: lanes 0-7 -> n0-7/k-lo, 8-15 -> n0-7/k-hi, 16-23 -> n8-15/k-lo, 24-31 -> n8-15/k-hi
    const uint32_t bPair0 = (uint32_t)((wn * WN + ((lane >> 4) << 3) + (lane & 7)) << 7)
                          + (((lane >> 3) & 1) << 4);

    load_stage(0, 0);
    CP_COMMIT();

    for (int c = 0; c < nch; c++){
        if (c + 1 < nch){
            load_stage((c + 1) << 5, (c + 1) & 1);
            CP_COMMIT();
            CP_WAIT1();
        } else {
            CP_WAIT0();
        }
        __syncthreads();

        const uint32_t ab = a32 + (uint32_t)(c & 1) * 16384u;
        const uint32_t bb = b32 + (uint32_t)(c & 1) * BSTRIDE;

#pragma unroll
        for (int kh = 0; kh < 2; kh++){
            const uint32_t hiOff = (uint32_t)(kh << 5);
            const uint32_t loOff = hiOff + 64;

            uint32_t ah[2][4], al[2][4];
#pragma unroll
            for (int mt = 0; mt < 2; mt++){
                uint32_t base = aRowOff0 + (uint32_t)(mt << 11);
                ldsm_x4(ah[mt][0], ah[mt][1], ah[mt][2], ah[mt][3],
                        ab + SWZ(base + hiOff));
                ldsm_x4(al[mt][0], al[mt][1], al[mt][2], al[mt][3],
                        ab + SWZ(base + loOff));
            }
            // B-hi pass: hh + lh combos (4 MMAs per n-tile, 2 n-tiles per ldsm_x4)
#pragma unroll
            for (int np = 0; np < NPAIR; np++){
                uint32_t b4[4];
                ldsm_x4(b4[0], b4[1], b4[2], b4[3],
                        bb + SWZ(bPair0 + (uint32_t)(np << 11) + hiOff));
                const int nt0 = 2 * np, nt1 = 2 * np + 1;
                mma16816(acc[0][nt0], ah[0], b4 + 0);
                mma16816(acc[1][nt0], ah[1], b4 + 0);
                mma16816(acc[0][nt0], al[0], b4 + 0);
                mma16816(acc[1][nt0], al[1], b4 + 0);
                mma16816(acc[0][nt1], ah[0], b4 + 2);
                mma16816(acc[1][nt1], ah[1], b4 + 2);
                mma16816(acc[0][nt1], al[0], b4 + 2);
                mma16816(acc[1][nt1], al[1], b4 + 2);
            }
            // B-lo pass: hl combo (2 MMAs per n-tile)
#pragma unroll
            for (int np = 0; np < NPAIR; np++){
                uint32_t b4[4];
                ldsm_x4(b4[0], b4[1], b4[2], b4[3],
                        bb + SWZ(bPair0 + (uint32_t)(np << 11) + loOff));
                const int nt0 = 2 * np, nt1 = 2 * np + 1;
                mma16816(acc[0][nt0], ah[0], b4 + 0);
                mma16816(acc[1][nt0], ah[1], b4 + 0);
                mma16816(acc[0][nt1], ah[0], b4 + 2);
                mma16816(acc[1][nt1], ah[1], b4 + 2);
            }
        }
        __syncthreads();
    }

    const int r0 = wm * 32 + (lane >> 2);
    const int cc = (lane & 3) * 2;
#pragma unroll
    for (int mt = 0; mt < 2; mt++){
#pragma unroll
        for (int nt = 0; nt < NTILES; nt++){
            const int col = wn * WN + nt * 8 + cc;
            float* p0 = C + (size_t)(r0 + mt * 16) * ldc + col;
            float* p1 = C + (size_t)(r0 + mt * 16 + 8) * ldc + col;
            *reinterpret_cast<float2*>(p0) = make_float2(acc[mt][nt][0], acc[mt][nt][1]);
            *reinterpret_cast<float2*>(p1) = make_float2(acc[mt][nt][2], acc[mt][nt][3]);
        }
    }
}

#define SM128 (32768 + 2 * 128 * 128)   // 65536
#define SM64  (32768 + 2 * 64 * 128)    // 49152

// ============================ GEMM wrappers ===============================
__global__ __launch_bounds__(256)
void k_proj(const __nv_bfloat16* __restrict__ Ah, const __nv_bfloat16* __restrict__ Al,
            const __nv_bfloat16* __restrict__ Bh, const __nv_bfloat16* __restrict__ Bl,
            float* __restrict__ C)
{
    size_t ao = (size_t)blockIdx.y * 128 * DM;
    size_t bo = (size_t)blockIdx.x * 128 * DM;
    float* Cp = C + (size_t)blockIdx.y * 128 * DM + blockIdx.x * 128;
    gemm_core<128>(Ah + ao, Al + ao, DM, Bh + bo, Bl + bo, DM, Cp, DM, DM);
}

__global__ __launch_bounds__(256)
void k_proj_cat(const __nv_bfloat16* __restrict__ Mh, const __nv_bfloat16* __restrict__ Ml,
                const __nv_bfloat16* __restrict__ Hh, const __nv_bfloat16* __restrict__ Hl,
                const __nv_bfloat16* __restrict__ Bh, const __nv_bfloat16* __restrict__ Bl,
                float* __restrict__ C)
{
    const int b = blockIdx.z, m0 = blockIdx.y * 128;
    const __nv_bfloat16 *Ah, *Al;
    if (m0 < ML){ size_t o = ((size_t)b * ML + m0) * DM; Ah = Mh + o; Al = Ml + o; }
    else        { size_t o = ((size_t)b * QL + (m0 - ML)) * DM; Ah = Hh + o; Al = Hl + o; }
    size_t bo = (size_t)blockIdx.x * 128 * DM;
    float* Cp = C + ((size_t)b * KL + m0) * DM + blockIdx.x * 128;
    gemm_core<128>(Ah, Al, DM, Bh + bo, Bl + bo, DM, Cp, DM, DM);
}

__global__ __launch_bounds__(256)
void k_score(const __nv_bfloat16* __restrict__ Qh, const __nv_bfloat16* __restrict__ Ql,
             const __nv_bfloat16* __restrict__ Kh, const __nv_bfloat16* __restrict__ Kl2,
             float* __restrict__ Sout, int kBat)
{
    const int z = blockIdx.z, b = z >> 4, h = z & 15;
    const int i0 = blockIdx.y * 128, j0 = blockIdx.x * 128;
    size_t ao = ((size_t)(b * QL + i0)) * DM + h * DH;
    size_t bo = kBat ? ((size_t)(b * KL + j0)) * DM + h * DH
                     : (size_t)j0 * DM + h * DH;
    float* Cp = Sout + ((size_t)z * QL + i0) * KL + j0;
    gemm_core<128>(Qh + ao, Ql + ao, DM, Kh + bo, Kl2 + bo, DM, Cp, KL, DH);
}

__global__ __launch_bounds__(256)
void k_av(const __nv_bfloat16* __restrict__ Ph, const __nv_bfloat16* __restrict__ Pl,
          const __nv_bfloat16* __restrict__ Vh, const __nv_bfloat16* __restrict__ Vl,
          float* __restrict__ AV)
{
    const int z = blockIdx.z, b = z >> 4, h = z & 15;
    const int i0 = blockIdx.y * 128;
    size_t ao = ((size_t)z * QL + i0) * KL;
    size_t bo = ((size_t)b * DM + h * DH) * KL;
    float* Cp = AV + ((size_t)(b * QL + i0)) * DM + h * DH;
    gemm_core<64>(Ph + ao, Pl + ao, KL, Vh + bo, Vl + bo, KL, Cp, DM, KL);
}

// ============================ conversions =================================
__device__ __forceinline__ void split1(float x, __nv_bfloat16& h, __nv_bfloat16& l){
    h = __float2bfloat16(x);
    l = __float2bfloat16(x - __bfloat162float(h));
}

__global__ __launch_bounds__(256)
void k_split(const float* __restrict__ x, __nv_bfloat16* __restrict__ h,
             __nv_bfloat16* __restrict__ l, size_t n)
{
    size_t i = ((size_t)blockIdx.x * 256 + threadIdx.x) * 4;
    if (i >= n) return;
    float4 v = *reinterpret_cast<const float4*>(x + i);
    __nv_bfloat16 h0, h1, h2, h3, l0, l1, l2, l3;
    split1(v.x, h0, l0); split1(v.y, h1, l1);
    split1(v.z, h2, l2); split1(v.w, h3, l3);
    *reinterpret_cast<__nv_bfloat162*>(h + i)     = __halves2bfloat162(h0, h1);
    *reinterpret_cast<__nv_bfloat162*>(h + i + 2) = __halves2bfloat162(h2, h3);
    *reinterpret_cast<__nv_bfloat162*>(l + i)     = __halves2bfloat162(l0, l1);
    *reinterpret_cast<__nv_bfloat162*>(l + i + 2) = __halves2bfloat162(l2, l3);
}

__global__ __launch_bounds__(256)
void k_split_qbias(const float* __restrict__ q,
                   const float* __restrict__ b1, const float* __restrict__ b2,
                   __nv_bfloat16* __restrict__ h1, __nv_bfloat16* __restrict__ l1,
                   __nv_bfloat16* __restrict__ h2, __nv_bfloat16* __restrict__ l2,
                   size_t n)
{
    size_t i = ((size_t)blockIdx.x * 256 + threadIdx.x) * 4;
    if (i >= n) return;
    const int col = (int)(i & (DM - 1));
    float4 v = *reinterpret_cast<const float4*>(q + i);
    float4 a = *reinterpret_cast<const float4*>(b1 + col);
    float4 c = *reinterpret_cast<const float4*>(b2 + col);
    __nv_bfloat16 h0, h1b, h2b, h3, l0, l1b, l2b, l3;
    split1(v.x + a.x, h0, l0);  split1(v.y + a.y, h1b, l1b);
    split1(v.z + a.z, h2b, l2b); split1(v.w + a.w, h3, l3);
    *reinterpret_cast<__nv_bfloat162*>(h1 + i)     = __halves2bfloat162(h0, h1b);
    *reinterpret_cast<__nv_bfloat162*>(h1 + i + 2) = __halves2bfloat162(h2b, h3);
    *reinterpret_cast<__nv_bfloat162*>(l1 + i)     = __halves2bfloat162(l0, l1b);
    *reinterpret_cast<__nv_bfloat162*>(l1 + i + 2) = __halves2bfloat162(l2b, l3);
    split1(v.x + c.x, h0, l0);  split1(v.y + c.y, h1b, l1b);
    split1(v.z + c.z, h2b, l2b); split1(v.w + c.w, h3, l3);
    *reinterpret_cast<__nv_bfloat162*>(h2 + i)     = __halves2bfloat162(h0, h1b);
    *reinterpret_cast<__nv_bfloat162*>(h2 + i + 2) = __halves2bfloat162(h2b, h3);
    *reinterpret_cast<__nv_bfloat162*>(l2 + i)     = __halves2bfloat162(l0, l1b);
    *reinterpret_cast<__nv_bfloat162*>(l2 + i + 2) = __halves2bfloat162(l2b, l3);
}

// out[b][c][r] = split(x[b][r][c]) ; grid (C/32, R/32, batch), block (32,8)
__global__ __launch_bounds__(256)
void k_tsplit(const float* __restrict__ x, __nv_bfloat16* __restrict__ th,
              __nv_bfloat16* __restrict__ tl, int R, int C)
{
    __shared__ float t[32][33];
    const int bz = blockIdx.z;
    const float* xb = x + (size_t)bz * R * C;
    __nv_bfloat16* ph = th + (size_t)bz * R * C;
    __nv_bfloat16* pl = tl + (size_t)bz * R * C;
    const int c0 = blockIdx.x * 32, r0 = blockIdx.y * 32;
    const int tx = threadIdx.x, ty = threadIdx.y;
    for (int i = ty; i < 32; i += 8)
        t[i][tx] = xb[(size_t)(r0 + i) * C + c0 + tx];
    __syncthreads();
    for (int i = ty; i < 32; i += 8){
        __nv_bfloat16 h, l; split1(t[tx][i], h, l);
        ph[(size_t)(c0 + i) * R + r0 + tx] = h;
        pl[(size_t)(c0 + i) * R + r0 + tx] = l;
    }
}

// ============================ softmax =====================================
__global__ __launch_bounds__(256)
void k_softmax(const float* __restrict__ S, const float* __restrict__ BD,
               __nv_bfloat16* __restrict__ Ph, __nv_bfloat16* __restrict__ Pl)
{
    const int row = blockIdx.x;
    const int i   = row & (QL - 1);
    const float* srow = S + (size_t)row * KL;
    const float* x0 = BD + (size_t)row * KL;
    const float* x1 = x0 + KL;

    const int tid = threadIdx.x, lane = tid & 31, warp = tid >> 5;
    __shared__ float red[8];

    float sc[8];
    float mx = -1e30f;
#pragma unroll
    for (int c = 0; c < 8; c++){
        const int j = c * 256 + tid;
        const int d = j - i;
        float bdv;
        if (d <= QL)           bdv = x0[j - i + (QL - 1)];
        else if (d == QL + 1)  bdv = 0.0f;
        else                   bdv = x1[j - i - (QL + 2)];
        const float v = (srow[j] + bdv) * 0.125f;
        sc[c] = v;
        mx = fmaxf(mx, v);
    }
#pragma unroll
    for (int o = 16; o > 0; o >>= 1) mx = fmaxf(mx, __shfl_xor_sync(0xffffffffu, mx, o));
    if (lane == 0) red[warp] = mx;
    __syncthreads();
    float rowmax = red[0];
#pragma unroll
    for (int w = 1; w < 8; w++) rowmax = fmaxf(rowmax, red[w]);
    __syncthreads();

    float sum = 0.0f;
#pragma unroll
    for (int c = 0; c < 8; c++){ sc[c] = __expf(sc[c] - rowmax); sum += sc[c]; }
#pragma unroll
    for (int o = 16; o > 0; o >>= 1) sum += __shfl_xor_sync(0xffffffffu, sum, o);
    if (lane == 0) red[warp] = sum;
    __syncthreads();
    float rowsum = 0.0f;
#pragma unroll
    for (int w = 0; w < 8; w++) rowsum += red[w];
    const float inv = 1.0f / rowsum;

    __nv_bfloat16* ph = Ph + (size_t)row * KL;
    __nv_bfloat16* pl = Pl + (size_t)row * KL;
#pragma unroll
    for (int c = 0; c < 8; c++){
        const int j = c * 256 + tid;
        __nv_bfloat16 h, l; split1(sc[c] * inv, h, l);
        ph[j] = h; pl[j] = l;
    }
}

// ============================ launch ======================================
extern "C" void kernel_launch(void* const* d_in, const int* in_sizes, int n_in,
                              void* d_out, int out_size)
{
    const float* h_in  = (const float*)d_in[0];
    const float* mem_p = (const float*)d_in[1];
    const float* r_p   = (const float*)d_in[2];
    const float* W[5]  = { (const float*)d_in[3], (const float*)d_in[4],
                           (const float*)d_in[5], (const float*)d_in[6],
                           (const float*)d_in[7] };   // Wq, Wk, Wv, Wr, Wo
    const float* rwb   = (const float*)d_in[8];
    const float* rrb   = (const float*)d_in[9];
    float* out = (float*)d_out;

    __nv_bfloat16* bf; float* fp;
    cudaGetSymbolAddress((void**)&bf, g_bf);
    cudaGetSymbolAddress((void**)&fp, g_f);

    cudaFuncSetAttribute(k_proj,     cudaFuncAttributeMaxDynamicSharedMemorySize, SM128);
    cudaFuncSetAttribute(k_proj_cat, cudaFuncAttributeMaxDynamicSharedMemorySize, SM128);
    cudaFuncSetAttribute(k_score,    cudaFuncAttributeMaxDynamicSharedMemorySize, SM128);
    cudaFuncSetAttribute(k_av,       cudaFuncAttributeMaxDynamicSharedMemorySize, SM64);

    // 1) split inputs
    k_split<<<2048, 256>>>(h_in,  bf + oHSPh, bf + oHSPl, SZ_2M);
    k_split<<<2048, 256>>>(mem_p, bf + oMSPh, bf + oMSPl, SZ_2M);
    k_split<<<2048, 256>>>(r_p,   bf + oRSPh, bf + oRSPl, SZ_2M);

    // 2) transpose+split weights: Wt[n][k]
    for (int w = 0; w < 5; w++){
        __nv_bfloat16* th = bf + oWT + (size_t)w * 2 * SZ_1M;
        k_tsplit<<<dim3(32, 32, 1), dim3(32, 8)>>>(W[w], th, th + SZ_1M, 1024, 1024);
    }
    const __nv_bfloat16 *wq = bf + oWT,            *wk = bf + oWT + 2 * SZ_1M,
                        *wv = bf + oWT + 4 * SZ_1M, *wr = bf + oWT + 6 * SZ_1M,
                        *wo = bf + oWT + 8 * SZ_1M;

    // 3) projections (mma.sync)
    k_proj<<<dim3(8, 16), 256, SM128>>>(bf + oHSPh, bf + oHSPl, wq, wq + SZ_1M, fp + fQ);
    k_proj_cat<<<dim3(8, 16, 2), 256, SM128>>>(bf + oMSPh, bf + oMSPl, bf + oHSPh, bf + oHSPl,
                                               wk, wk + SZ_1M, fp + fK);
    k_proj_cat<<<dim3(8, 16, 2), 256, SM128>>>(bf + oMSPh, bf + oMSPl, bf + oHSPh, bf + oHSPl,
                                               wv, wv + SZ_1M, fp + fV);
    k_proj<<<dim3(8, 16), 256, SM128>>>(bf + oRSPh, bf + oRSPl, wr, wr + SZ_1M, fp + fR);

    // 4) split projections for score/av GEMMs
    k_split_qbias<<<2048, 256>>>(fp + fQ, rwb, rrb,
                                 bf + oQWh, bf + oQWl, bf + oQRh, bf + oQRl, SZ_2M);
    k_split<<<4096, 256>>>(fp + fK, bf + oKh,  bf + oKl,  SZ_4M);
    k_split<<<2048, 256>>>(fp + fR, bf + oRHh, bf + oRHl, SZ_2M);
    k_tsplit<<<dim3(32, 64, 2), dim3(32, 8)>>>(fp + fV, bf + oVTh, bf + oVTl, KL, DM);

    // 5) scores (fp32 out)
    k_score<<<dim3(16, 8, 32), 256, SM128>>>(bf + oQWh, bf + oQWl, bf + oKh,  bf + oKl,
                                             fp + fS, 1);
    k_score<<<dim3(16, 8, 32), 256, SM128>>>(bf + oQRh, bf + oQRl, bf + oRHh, bf + oRHl,
                                             fp + fBD, 0);

    // 6) fused rel_shift + softmax -> split probs
    k_softmax<<<B_SZ * NH * QL, 256>>>(fp + fS, fp + fBD, bf + oPh, bf + oPl);

    // 7) attn_vec = prob @ v
    k_av<<<dim3(1, 8, 32), 256, SM64>>>(bf + oPh, bf + oPl, bf + oVTh, bf + oVTl, fp + fAV);

    // 8) out = attn_vec @ Wo
    k_split<<<2048, 256>>>(fp + fAV, bf + oAVh, bf + oAVl, SZ_2M);
    k_proj<<<dim3(8, 16), 256, SM128>>>(bf + oAVh, bf + oAVl, wo, wo + SZ_1M, out);
}

// round 8
// speedup vs baseline: 1.6100x; 1.0452x over previous
#include <cuda_runtime.h>
#include <cuda_bf16.h>
#include <cstdint>
#include <cstddef>

#define B_SZ 2
#define QL   1024
#define ML   1024
#define KL   2048
#define DM   1024
#define NH   16
#define DH   64

// ============================ helpers =====================================
__device__ __forceinline__ uint32_t smem_u32(const void* p){
    uint32_t a;
    asm("{ .reg .u64 t; cvta.to.shared.u64 t, %1; cvt.u32.u64 %0, t; }" : "=r"(a) : "l"(p));
    return a;
}

#define SWZ(o) ((o) ^ (((o) >> 3) & 0x70))

__device__ __forceinline__ void ldsm_x4(uint32_t& r0, uint32_t& r1, uint32_t& r2,
                                        uint32_t& r3, uint32_t a){
    asm volatile("ldmatrix.sync.aligned.m8n8.x4.shared.b16 {%0,%1,%2,%3},[%4];"
                 : "=r"(r0), "=r"(r1), "=r"(r2), "=r"(r3) : "r"(a));
}
__device__ __forceinline__ void mma16816(float* c, const uint32_t* a, const uint32_t* b){
    asm volatile(
        "mma.sync.aligned.m16n8k16.row.col.f32.bf16.bf16.f32 "
        "{%0,%1,%2,%3},{%4,%5,%6,%7},{%8,%9},{%0,%1,%2,%3};"
        : "+f"(c[0]), "+f"(c[1]), "+f"(c[2]), "+f"(c[3])
        : "r"(a[0]), "r"(a[1]), "r"(a[2]), "r"(a[3]), "r"(b[0]), "r"(b[1]));
}

// ============================ scratch pools ===============================
#define SZ_1M ((size_t)1024 * 1024)
#define SZ_2M ((size_t)2048 * 1024)
#define SZ_4M ((size_t)4096 * 1024)
#define SZ_P  ((size_t)B_SZ * NH * QL * KL)

constexpr size_t oHSPh = 0,               oHSPl = oHSPh + SZ_2M;
constexpr size_t oMSPh = oHSPl + SZ_2M,   oMSPl = oMSPh + SZ_2M;
constexpr size_t oRSPh = oMSPl + SZ_2M,   oRSPl = oRSPh + SZ_2M;
constexpr size_t oWT   = oRSPl + SZ_2M;                       // 5 x (hi 1M | lo 1M)
constexpr size_t oQWh  = oWT + 10 * SZ_1M, oQWl = oQWh + SZ_2M;
constexpr size_t oQRh  = oQWl + SZ_2M,    oQRl = oQRh + SZ_2M;
constexpr size_t oKh   = oQRl + SZ_2M,    oKl  = oKh + SZ_4M;
constexpr size_t oRHh  = oKl + SZ_4M,     oRHl = oRHh + SZ_2M;
constexpr size_t oVTh  = oRHl + SZ_2M,    oVTl = oVTh + SZ_4M;
constexpr size_t oPh   = oVTl + SZ_4M,    oPl  = oPh + SZ_P;
constexpr size_t oAVh  = oPl + SZ_P,      oAVl = oAVh + SZ_2M;
constexpr size_t BF_TOTAL = oAVl + SZ_2M;

constexpr size_t fQ  = 0;
constexpr size_t fK  = fQ + SZ_2M;
constexpr size_t fV  = fK + SZ_4M;
constexpr size_t fR  = fV + SZ_4M;
constexpr size_t fAV = fR + SZ_2M;
constexpr size_t fS  = fAV + SZ_2M;
constexpr size_t fBD = fS + SZ_P;
constexpr size_t F_TOTAL = fBD + SZ_P;

__device__ __nv_bfloat16 g_bf[BF_TOTAL];
__device__ float         g_f [F_TOTAL];

// ============================ GEMM core (mma.sync) ========================
// C[128, NT] = (Ahi+Alo)[128,K] * (Bhi+Blo)[NT,K]^T, dropping lo*lo.
// smem rows are 128B: [32 hi bf16 | 32 lo bf16] per 32-element K chunk, SW128.
// 8 warps: warp_m = wid&3 (32 rows), warp_n = wid>>2 (NT/2 cols).
// R4 structure (register prefetch + single smem buffer); B frags via ldsm_x4.
template <int NT>
__device__ __forceinline__ void gemm_core(
    const __nv_bfloat16* __restrict__ Ahi, const __nv_bfloat16* __restrict__ Alo, int lda,
    const __nv_bfloat16* __restrict__ Bhi, const __nv_bfloat16* __restrict__ Blo, int ldb,
    float* __restrict__ C, int ldc, int K)
{
    __shared__ __align__(1024) uint8_t sA[128 * 128];
    __shared__ __align__(1024) uint8_t sB[NT * 128];

    const int tid  = threadIdx.x;
    const int wid  = tid >> 5;
    const int lane = tid & 31;
    const int wm   = wid & 3;
    const int wn   = wid >> 2;
    constexpr int WN     = NT / 2;
    constexpr int NTILES = WN / 8;
    constexpr int NPAIR  = NTILES / 2;
    constexpr int BSEG   = NT / 32;

    const uint32_t a32 = smem_u32(sA), b32 = smem_u32(sB);

    float acc[2][NTILES][4];
#pragma unroll
    for (int mt = 0; mt < 2; mt++)
#pragma unroll
        for (int nt = 0; nt < NTILES; nt++)
#pragma unroll
            for (int q = 0; q < 4; q++) acc[mt][nt][q] = 0.0f;

    uint4 pa[4], pb[BSEG];
    const int nch = K >> 5;

    auto ldg_chunk = [&](int k0){
#pragma unroll
        for (int i = 0; i < 4; i++){
            int s = tid + (i << 8); int row = s >> 3, j = s & 7;
            const __nv_bfloat16* p = (j < 4)
                ? Ahi + (size_t)row * lda + k0 + j * 8
                : Alo + (size_t)row * lda + k0 + (j - 4) * 8;
            pa[i] = *reinterpret_cast<const uint4*>(p);
        }
#pragma unroll
        for (int i = 0; i < BSEG; i++){
            int s = tid + (i << 8); int row = s >> 3, j = s & 7;
            const __nv_bfloat16* p = (j < 4)
                ? Bhi + (size_t)row * ldb + k0 + j * 8
                : Blo + (size_t)row * ldb + k0 + (j - 4) * 8;
            pb[i] = *reinterpret_cast<const uint4*>(p);
        }
    };

    // Per-lane ldmatrix base offsets
    const uint32_t aRowOff0 = (uint32_t)((wm * 32 + (lane & 15)) << 7) + ((lane >> 4) << 4);
    // x4 B: lanes 0-7 n-tile0/k-lo, 8-15 n-tile0/k-hi, 16-23 n-tile1/k-lo, 24-31 n-tile1/k-hi
    const uint32_t bPair0 = (uint32_t)((wn * WN + ((lane >> 4) << 3) + (lane & 7)) << 7)
                          + (((lane >> 3) & 1) << 4);

    ldg_chunk(0);

    for (int c = 0; c < nch; c++){
        // store prefetched chunk to smem (swizzled)
#pragma unroll
        for (int i = 0; i < 4; i++){
            int s = tid + (i << 8);
            uint32_t off = (uint32_t)((s >> 3) << 7) + (uint32_t)((s & 7) << 4);
            *reinterpret_cast<uint4*>(sA + SWZ(off)) = pa[i];
        }
#pragma unroll
        for (int i = 0; i < BSEG; i++){
            int s = tid + (i << 8);
            uint32_t off = (uint32_t)((s >> 3) << 7) + (uint32_t)((s & 7) << 4);
            *reinterpret_cast<uint4*>(sB + SWZ(off)) = pb[i];
        }
        __syncthreads();

        if (c + 1 < nch) ldg_chunk((c + 1) << 5);   // LDG overlaps MMA

#pragma unroll
        for (int kh = 0; kh < 2; kh++){
            const uint32_t hiOff = (uint32_t)(kh << 5);
            const uint32_t loOff = hiOff + 64;

            uint32_t ah[2][4], al[2][4];
#pragma unroll
            for (int mt = 0; mt < 2; mt++){
                uint32_t base = aRowOff0 + (uint32_t)(mt << 11);
                ldsm_x4(ah[mt][0], ah[mt][1], ah[mt][2], ah[mt][3],
                        a32 + SWZ(base + hiOff));
                ldsm_x4(al[mt][0], al[mt][1], al[mt][2], al[mt][3],
                        a32 + SWZ(base + loOff));
            }
            // B-hi pass: hh + lh combos (two n-tiles per ldsm_x4)
#pragma unroll
            for (int np = 0; np < NPAIR; np++){
                uint32_t b4[4];
                ldsm_x4(b4[0], b4[1], b4[2], b4[3],
                        b32 + SWZ(bPair0 + (uint32_t)(np << 11) + hiOff));
                const int nt0 = 2 * np, nt1 = 2 * np + 1;
                mma16816(acc[0][nt0], ah[0], b4 + 0);
                mma16816(acc[1][nt0], ah[1], b4 + 0);
                mma16816(acc[0][nt0], al[0], b4 + 0);
                mma16816(acc[1][nt0], al[1], b4 + 0);
                mma16816(acc[0][nt1], ah[0], b4 + 2);
                mma16816(acc[1][nt1], ah[1], b4 + 2);
                mma16816(acc[0][nt1], al[0], b4 + 2);
                mma16816(acc[1][nt1], al[1], b4 + 2);
            }
            // B-lo pass: hl combo
#pragma unroll
            for (int np = 0; np < NPAIR; np++){
                uint32_t b4[4];
                ldsm_x4(b4[0], b4[1], b4[2], b4[3],
                        b32 + SWZ(bPair0 + (uint32_t)(np << 11) + loOff));
                const int nt0 = 2 * np, nt1 = 2 * np + 1;
                mma16816(acc[0][nt0], ah[0], b4 + 0);
                mma16816(acc[1][nt0], ah[1], b4 + 0);
                mma16816(acc[0][nt1], ah[0], b4 + 2);
                mma16816(acc[1][nt1], ah[1], b4 + 2);
            }
        }
        __syncthreads();
    }

    // epilogue: fp32 stores
    const int r0 = wm * 32 + (lane >> 2);
    const int cc = (lane & 3) * 2;
#pragma unroll
    for (int mt = 0; mt < 2; mt++){
#pragma unroll
        for (int nt = 0; nt < NTILES; nt++){
            const int col = wn * WN + nt * 8 + cc;
            float* p0 = C + (size_t)(r0 + mt * 16) * ldc + col;
            float* p1 = C + (size_t)(r0 + mt * 16 + 8) * ldc + col;
            *reinterpret_cast<float2*>(p0) = make_float2(acc[mt][nt][0], acc[mt][nt][1]);
            *reinterpret_cast<float2*>(p1) = make_float2(acc[mt][nt][2], acc[mt][nt][3]);
        }
    }
}

// ============================ GEMM wrappers ===============================
__global__ __launch_bounds__(256)
void k_proj(const __nv_bfloat16* __restrict__ Ah, const __nv_bfloat16* __restrict__ Al,
            const __nv_bfloat16* __restrict__ Bh, const __nv_bfloat16* __restrict__ Bl,
            float* __restrict__ C)
{
    size_t ao = (size_t)blockIdx.y * 128 * DM;
    size_t bo = (size_t)blockIdx.x * 128 * DM;
    float* Cp = C + (size_t)blockIdx.y * 128 * DM + blockIdx.x * 128;
    gemm_core<128>(Ah + ao, Al + ao, DM, Bh + bo, Bl + bo, DM, Cp, DM, DM);
}

__global__ __launch_bounds__(256)
void k_proj_cat(const __nv_bfloat16* __restrict__ Mh, const __nv_bfloat16* __restrict__ Ml,
                const __nv_bfloat16* __restrict__ Hh, const __nv_bfloat16* __restrict__ Hl,
                const __nv_bfloat16* __restrict__ Bh, const __nv_bfloat16* __restrict__ Bl,
                float* __restrict__ C)
{
    const int b = blockIdx.z, m0 = blockIdx.y * 128;
    const __nv_bfloat16 *Ah, *Al;
    if (m0 < ML){ size_t o = ((size_t)b * ML + m0) * DM; Ah = Mh + o; Al = Ml + o; }
    else        { size_t o = ((size_t)b * QL + (m0 - ML)) * DM; Ah = Hh + o; Al = Hl + o; }
    size_t bo = (size_t)blockIdx.x * 128 * DM;
    float* Cp = C + ((size_t)b * KL + m0) * DM + blockIdx.x * 128;
    gemm_core<128>(Ah, Al, DM, Bh + bo, Bl + bo, DM, Cp, DM, DM);
}

__global__ __launch_bounds__(256)
void k_score(const __nv_bfloat16* __restrict__ Qh, const __nv_bfloat16* __restrict__ Ql,
             const __nv_bfloat16* __restrict__ Kh, const __nv_bfloat16* __restrict__ Kl2,
             float* __restrict__ Sout, int kBat)
{
    const int z = blockIdx.z, b = z >> 4, h = z & 15;
    const int i0 = blockIdx.y * 128, j0 = blockIdx.x * 128;
    size_t ao = ((size_t)(b * QL + i0)) * DM + h * DH;
    size_t bo = kBat ? ((size_t)(b * KL + j0)) * DM + h * DH
                     : (size_t)j0 * DM + h * DH;
    float* Cp = Sout + ((size_t)z * QL + i0) * KL + j0;
    gemm_core<128>(Qh + ao, Ql + ao, DM, Kh + bo, Kl2 + bo, DM, Cp, KL, DH);
}

__global__ __launch_bounds__(256)
void k_av(const __nv_bfloat16* __restrict__ Ph, const __nv_bfloat16* __restrict__ Pl,
          const __nv_bfloat16* __restrict__ Vh, const __nv_bfloat16* __restrict__ Vl,
          float* __restrict__ AV)
{
    const int z = blockIdx.z, b = z >> 4, h = z & 15;
    const int i0 = blockIdx.y * 128;
    size_t ao = ((size_t)z * QL + i0) * KL;
    size_t bo = ((size_t)b * DM + h * DH) * KL;
    float* Cp = AV + ((size_t)(b * QL + i0)) * DM + h * DH;
    gemm_core<64>(Ph + ao, Pl + ao, KL, Vh + bo, Vl + bo, KL, Cp, DM, KL);
}

// ============================ conversions =================================
__device__ __forceinline__ void split1(float x, __nv_bfloat16& h, __nv_bfloat16& l){
    h = __float2bfloat16(x);
    l = __float2bfloat16(x - __bfloat162float(h));
}

__global__ __launch_bounds__(256)
void k_split(const float* __restrict__ x, __nv_bfloat16* __restrict__ h,
             __nv_bfloat16* __restrict__ l, size_t n)
{
    size_t i = ((size_t)blockIdx.x * 256 + threadIdx.x) * 4;
    if (i >= n) return;
    float4 v = *reinterpret_cast<const float4*>(x + i);
    __nv_bfloat16 h0, h1, h2, h3, l0, l1, l2, l3;
    split1(v.x, h0, l0); split1(v.y, h1, l1);
    split1(v.z, h2, l2); split1(v.w, h3, l3);
    *reinterpret_cast<__nv_bfloat162*>(h + i)     = __halves2bfloat162(h0, h1);
    *reinterpret_cast<__nv_bfloat162*>(h + i + 2) = __halves2bfloat162(h2, h3);
    *reinterpret_cast<__nv_bfloat162*>(l + i)     = __halves2bfloat162(l0, l1);
    *reinterpret_cast<__nv_bfloat162*>(l + i + 2) = __halves2bfloat162(l2, l3);
}

__global__ __launch_bounds__(256)
void k_split_qbias(const float* __restrict__ q,
                   const float* __restrict__ b1, const float* __restrict__ b2,
                   __nv_bfloat16* __restrict__ h1, __nv_bfloat16* __restrict__ l1,
                   __nv_bfloat16* __restrict__ h2, __nv_bfloat16* __restrict__ l2,
                   size_t n)
{
    size_t i = ((size_t)blockIdx.x * 256 + threadIdx.x) * 4;
    if (i >= n) return;
    const int col = (int)(i & (DM - 1));
    float4 v = *reinterpret_cast<const float4*>(q + i);
    float4 a = *reinterpret_cast<const float4*>(b1 + col);
    float4 c = *reinterpret_cast<const float4*>(b2 + col);
    __nv_bfloat16 h0, h1b, h2b, h3, l0, l1b, l2b, l3;
    split1(v.x + a.x, h0, l0);  split1(v.y + a.y, h1b, l1b);
    split1(v.z + a.z, h2b, l2b); split1(v.w + a.w, h3, l3);
    *reinterpret_cast<__nv_bfloat162*>(h1 + i)     = __halves2bfloat162(h0, h1b);
    *reinterpret_cast<__nv_bfloat162*>(h1 + i + 2) = __halves2bfloat162(h2b, h3);
    *reinterpret_cast<__nv_bfloat162*>(l1 + i)     = __halves2bfloat162(l0, l1b);
    *reinterpret_cast<__nv_bfloat162*>(l1 + i + 2) = __halves2bfloat162(l2b, l3);
    split1(v.x + c.x, h0, l0);  split1(v.y + c.y, h1b, l1b);
    split1(v.z + c.z, h2b, l2b); split1(v.w + c.w, h3, l3);
    *reinterpret_cast<__nv_bfloat162*>(h2 + i)     = __halves2bfloat162(h0, h1b);
    *reinterpret_cast<__nv_bfloat162*>(h2 + i + 2) = __halves2bfloat162(h2b, h3);
    *reinterpret_cast<__nv_bfloat162*>(l2 + i)     = __halves2bfloat162(l0, l1b);
    *reinterpret_cast<__nv_bfloat162*>(l2 + i + 2) = __halves2bfloat162(l2b, l3);
}

// out[b][c][r] = split(x[b][r][c]) ; grid (C/32, R/32, batch), block (32,8)
__global__ __launch_bounds__(256)
void k_tsplit(const float* __restrict__ x, __nv_bfloat16* __restrict__ th,
              __nv_bfloat16* __restrict__ tl, int R, int C)
{
    __shared__ float t[32][33];
    const int bz = blockIdx.z;
    const float* xb = x + (size_t)bz * R * C;
    __nv_bfloat16* ph = th + (size_t)bz * R * C;
    __nv_bfloat16* pl = tl + (size_t)bz * R * C;
    const int c0 = blockIdx.x * 32, r0 = blockIdx.y * 32;
    const int tx = threadIdx.x, ty = threadIdx.y;
    for (int i = ty; i < 32; i += 8)
        t[i][tx] = xb[(size_t)(r0 + i) * C + c0 + tx];
    __syncthreads();
    for (int i = ty; i < 32; i += 8){
        __nv_bfloat16 h, l; split1(t[tx][i], h, l);
        ph[(size_t)(c0 + i) * R + r0 + tx] = h;
        pl[(size_t)(c0 + i) * R + r0 + tx] = l;
    }
}

// ============================ softmax =====================================
__global__ __launch_bounds__(256)
void k_softmax(const float* __restrict__ S, const float* __restrict__ BD,
               __nv_bfloat16* __restrict__ Ph, __nv_bfloat16* __restrict__ Pl)
{
    const int row = blockIdx.x;
    const int i   = row & (QL - 1);
    const float* srow = S + (size_t)row * KL;
    const float* x0 = BD + (size_t)row * KL;
    const float* x1 = x0 + KL;

    const int tid = threadIdx.x, lane = tid & 31, warp = tid >> 5;
    __shared__ float red[8];

    float sc[8];
    float mx = -1e30f;
#pragma unroll
    for (int c = 0; c < 8; c++){
        const int j = c * 256 + tid;
        const int d = j - i;
        float bdv;
        if (d <= QL)           bdv = x0[j - i + (QL - 1)];
        else if (d == QL + 1)  bdv = 0.0f;
        else                   bdv = x1[j - i - (QL + 2)];
        const float v = (srow[j] + bdv) * 0.125f;
        sc[c] = v;
        mx = fmaxf(mx, v);
    }
#pragma unroll
    for (int o = 16; o > 0; o >>= 1) mx = fmaxf(mx, __shfl_xor_sync(0xffffffffu, mx, o));
    if (lane == 0) red[warp] = mx;
    __syncthreads();
    float rowmax = red[0];
#pragma unroll
    for (int w = 1; w < 8; w++) rowmax = fmaxf(rowmax, red[w]);
    __syncthreads();

    float sum = 0.0f;
#pragma unroll
    for (int c = 0; c < 8; c++){ sc[c] = __expf(sc[c] - rowmax); sum += sc[c]; }
#pragma unroll
    for (int o = 16; o > 0; o >>= 1) sum += __shfl_xor_sync(0xffffffffu, sum, o);
    if (lane == 0) red[warp] = sum;
    __syncthreads();
    float rowsum = 0.0f;
#pragma unroll
    for (int w = 0; w < 8; w++) rowsum += red[w];
    const float inv = 1.0f / rowsum;

    __nv_bfloat16* ph = Ph + (size_t)row * KL;
    __nv_bfloat16* pl = Pl + (size_t)row * KL;
#pragma unroll
    for (int c = 0; c < 8; c++){
        const int j = c * 256 + tid;
        __nv_bfloat16 h, l; split1(sc[c] * inv, h, l);
        ph[j] = h; pl[j] = l;
    }
}

// ============================ launch ======================================
extern "C" void kernel_launch(void* const* d_in, const int* in_sizes, int n_in,
                              void* d_out, int out_size)
{
    const float* h_in  = (const float*)d_in[0];
    const float* mem_p = (const float*)d_in[1];
    const float* r_p   = (const float*)d_in[2];
    const float* W[5]  = { (const float*)d_in[3], (const float*)d_in[4],
                           (const float*)d_in[5], (const float*)d_in[6],
                           (const float*)d_in[7] };   // Wq, Wk, Wv, Wr, Wo
    const float* rwb   = (const float*)d_in[8];
    const float* rrb   = (const float*)d_in[9];
    float* out = (float*)d_out;

    __nv_bfloat16* bf; float* fp;
    cudaGetSymbolAddress((void**)&bf, g_bf);
    cudaGetSymbolAddress((void**)&fp, g_f);

    // 1) split inputs
    k_split<<<2048, 256>>>(h_in,  bf + oHSPh, bf + oHSPl, SZ_2M);
    k_split<<<2048, 256>>>(mem_p, bf + oMSPh, bf + oMSPl, SZ_2M);
    k_split<<<2048, 256>>>(r_p,   bf + oRSPh, bf + oRSPl, SZ_2M);

    // 2) transpose+split weights: Wt[n][k]
    for (int w = 0; w < 5; w++){
        __nv_bfloat16* th = bf + oWT + (size_t)w * 2 * SZ_1M;
        k_tsplit<<<dim3(32, 32, 1), dim3(32, 8)>>>(W[w], th, th + SZ_1M, 1024, 1024);
    }
    const __nv_bfloat16 *wq = bf + oWT,            *wk = bf + oWT + 2 * SZ_1M,
                        *wv = bf + oWT + 4 * SZ_1M, *wr = bf + oWT + 6 * SZ_1M,
                        *wo = bf + oWT + 8 * SZ_1M;

    // 3) projections (mma.sync)
    k_proj<<<dim3(8, 16), 256>>>(bf + oHSPh, bf + oHSPl, wq, wq + SZ_1M, fp + fQ);
    k_proj_cat<<<dim3(8, 16, 2), 256>>>(bf + oMSPh, bf + oMSPl, bf + oHSPh, bf + oHSPl,
                                        wk, wk + SZ_1M, fp + fK);
    k_proj_cat<<<dim3(8, 16, 2), 256>>>(bf + oMSPh, bf + oMSPl, bf + oHSPh, bf + oHSPl,
                                        wv, wv + SZ_1M, fp + fV);
    k_proj<<<dim3(8, 16), 256>>>(bf + oRSPh, bf + oRSPl, wr, wr + SZ_1M, fp + fR);

    // 4) split projections for score/av GEMMs
    k_split_qbias<<<2048, 256>>>(fp + fQ, rwb, rrb,
                                 bf + oQWh, bf + oQWl, bf + oQRh, bf + oQRl, SZ_2M);
    k_split<<<4096, 256>>>(fp + fK, bf + oKh,  bf + oKl,  SZ_4M);
    k_split<<<2048, 256>>>(fp + fR, bf + oRHh, bf + oRHl, SZ_2M);
    k_tsplit<<<dim3(32, 64, 2), dim3(32, 8)>>>(fp + fV, bf + oVTh, bf + oVTl, KL, DM);

    // 5) scores (fp32 out)
    k_score<<<dim3(16, 8, 32), 256>>>(bf + oQWh, bf + oQWl, bf + oKh,  bf + oKl,
                                      fp + fS, 1);
    k_score<<<dim3(16, 8, 32), 256>>>(bf + oQRh, bf + oQRl, bf + oRHh, bf + oRHl,
                                      fp + fBD, 0);

    // 6) fused rel_shift + softmax -> split probs
    k_softmax<<<B_SZ * NH * QL, 256>>>(fp + fS, fp + fBD, bf + oPh, bf + oPl);

    // 7) attn_vec = prob @ v
    k_av<<<dim3(1, 8, 32), 256>>>(bf + oPh, bf + oPl, bf + oVTh, bf + oVTl, fp + fAV);

    // 8) out = attn_vec @ Wo
    k_split<<<2048, 256>>>(fp + fAV, bf + oAVh, bf + oAVl, SZ_2M);
    k_proj<<<dim3(8, 16), 256>>>(bf + oAVh, bf + oAVl, wo, wo + SZ_1M, out);
}

// round 9
// speedup vs baseline: 2.6906x; 1.6712x over previous
#include <cuda_runtime.h>
#include <cuda_fp16.h>
#include <cstdint>
#include <cstddef>

#define B_SZ 2
#define QL   1024
#define ML   1024
#define KL   2048
#define DM   1024
#define NH   16
#define DH   64

// ============================ helpers =====================================
__device__ __forceinline__ uint32_t smem_u32(const void* p){
    uint32_t a;
    asm("{ .reg .u64 t; cvta.to.shared.u64 t, %1; cvt.u32.u64 %0, t; }" : "=r"(a) : "l"(p));
    return a;
}

#define SWZ(o) ((o) ^ (((o) >> 3) & 0x70))

__device__ __forceinline__ void ldsm_x4(uint32_t& r0, uint32_t& r1, uint32_t& r2,
                                        uint32_t& r3, uint32_t a){
    asm volatile("ldmatrix.sync.aligned.m8n8.x4.shared.b16 {%0,%1,%2,%3},[%4];"
                 : "=r"(r0), "=r"(r1), "=r"(r2), "=r"(r3) : "r"(a));
}
__device__ __forceinline__ void ldsm_x2(uint32_t& r0, uint32_t& r1, uint32_t a){
    asm volatile("ldmatrix.sync.aligned.m8n8.x2.shared.b16 {%0,%1},[%2];"
                 : "=r"(r0), "=r"(r1) : "r"(a));
}
// fp16 MMA, fp32 accumulate
__device__ __forceinline__ void mma16816(float* c, const uint32_t* a, const uint32_t* b){
    asm volatile(
        "mma.sync.aligned.m16n8k16.row.col.f32.f16.f16.f32 "
        "{%0,%1,%2,%3},{%4,%5,%6,%7},{%8,%9},{%0,%1,%2,%3};"
        : "+f"(c[0]), "+f"(c[1]), "+f"(c[2]), "+f"(c[3])
        : "r"(a[0]), "r"(a[1]), "r"(a[2]), "r"(a[3]), "r"(b[0]), "r"(b[1]));
}

// ============================ scratch pools ===============================
#define SZ_1M ((size_t)1024 * 1024)
#define SZ_2M ((size_t)2048 * 1024)
#define SZ_4M ((size_t)4096 * 1024)
#define SZ_P  ((size_t)B_SZ * NH * QL * KL)

constexpr size_t oHSPh = 0,               oHSPl = oHSPh + SZ_2M;
constexpr size_t oMSPh = oHSPl + SZ_2M,   oMSPl = oMSPh + SZ_2M;
constexpr size_t oRSPh = oMSPl + SZ_2M,   oRSPl = oRSPh + SZ_2M;
constexpr size_t oWT   = oRSPl + SZ_2M;                       // 5 x (hi 1M | lo 1M)
constexpr size_t oQWh  = oWT + 10 * SZ_1M, oQWl = oQWh + SZ_2M;
constexpr size_t oQRh  = oQWl + SZ_2M,    oQRl = oQRh + SZ_2M;
constexpr size_t oKp   = oQRl + SZ_2M;                        // K plain fp16 (4M)
constexpr size_t oRHp  = oKp + SZ_4M;                         // R plain fp16 (2M)
constexpr size_t oVTh  = oRHp + SZ_2M,    oVTl = oVTh + SZ_4M;
constexpr size_t oPp   = oVTl + SZ_4M;                        // P plain fp16 (64M)
constexpr size_t oAVh  = oPp + SZ_P,      oAVl = oAVh + SZ_2M;
constexpr size_t HF_TOTAL = oAVl + SZ_2M;

constexpr size_t fQ  = 0;
constexpr size_t fK  = fQ + SZ_2M;
constexpr size_t fV  = fK + SZ_4M;
constexpr size_t fR  = fV + SZ_4M;
constexpr size_t fAV = fR + SZ_2M;
constexpr size_t fS  = fAV + SZ_2M;
constexpr size_t fBD = fS + SZ_P;
constexpr size_t F_TOTAL = fBD + SZ_P;

__device__ __half g_hf[HF_TOTAL];
__device__ float  g_f [F_TOTAL];

// ============================ GEMM core (3-combo, split x split) ==========
// C[128, NT] = (Ahi+Alo)[128,K] * (Bhi+Blo)[NT,K]^T, dropping lo*lo.
// smem rows 128B: [32 hi fp16 | 32 lo fp16] per 32-element K chunk, SW128.
// R4 structure: register prefetch, single smem buffer, ldsm_x2 B.
template <int NT>
__device__ __forceinline__ void gemm_core(
    const __half* __restrict__ Ahi, const __half* __restrict__ Alo, int lda,
    const __half* __restrict__ Bhi, const __half* __restrict__ Blo, int ldb,
    float* __restrict__ C, int ldc, int K)
{
    __shared__ __align__(1024) uint8_t sA[128 * 128];
    __shared__ __align__(1024) uint8_t sB[NT * 128];

    const int tid  = threadIdx.x;
    const int wid  = tid >> 5;
    const int lane = tid & 31;
    const int wm   = wid & 3;
    const int wn   = wid >> 2;
    constexpr int WN     = NT / 2;
    constexpr int NTILES = WN / 8;
    constexpr int BSEG   = NT / 32;

    const uint32_t a32 = smem_u32(sA), b32 = smem_u32(sB);

    float acc[2][NTILES][4];
#pragma unroll
    for (int mt = 0; mt < 2; mt++)
#pragma unroll
        for (int nt = 0; nt < NTILES; nt++)
#pragma unroll
            for (int q = 0; q < 4; q++) acc[mt][nt][q] = 0.0f;

    uint4 pa[4], pb[BSEG];
    const int nch = K >> 5;

    auto ldg_chunk = [&](int k0){
#pragma unroll
        for (int i = 0; i < 4; i++){
            int s = tid + (i << 8); int row = s >> 3, j = s & 7;
            const __half* p = (j < 4)
                ? Ahi + (size_t)row * lda + k0 + j * 8
                : Alo + (size_t)row * lda + k0 + (j - 4) * 8;
            pa[i] = *reinterpret_cast<const uint4*>(p);
        }
#pragma unroll
        for (int i = 0; i < BSEG; i++){
            int s = tid + (i << 8); int row = s >> 3, j = s & 7;
            const __half* p = (j < 4)
                ? Bhi + (size_t)row * ldb + k0 + j * 8
                : Blo + (size_t)row * ldb + k0 + (j - 4) * 8;
            pb[i] = *reinterpret_cast<const uint4*>(p);
        }
    };

    const uint32_t aRowOff0 = (uint32_t)((wm * 32 + (lane & 15)) << 7) + ((lane >> 4) << 4);
    const uint32_t bRowOff  = (uint32_t)((wn * WN + (lane & 7)) << 7) + (((lane >> 3) & 1) << 4);

    ldg_chunk(0);

    for (int c = 0; c < nch; c++){
#pragma unroll
        for (int i = 0; i < 4; i++){
            int s = tid + (i << 8);
            uint32_t off = (uint32_t)((s >> 3) << 7) + (uint32_t)((s & 7) << 4);
            *reinterpret_cast<uint4*>(sA + SWZ(off)) = pa[i];
        }
#pragma unroll
        for (int i = 0; i < BSEG; i++){
            int s = tid + (i << 8);
            uint32_t off = (uint32_t)((s >> 3) << 7) + (uint32_t)((s & 7) << 4);
            *reinterpret_cast<uint4*>(sB + SWZ(off)) = pb[i];
        }
        __syncthreads();

        if (c + 1 < nch) ldg_chunk((c + 1) << 5);

#pragma unroll
        for (int kh = 0; kh < 2; kh++){
            const uint32_t hiOff = (uint32_t)(kh << 5);
            const uint32_t loOff = hiOff + 64;

            uint32_t ah[2][4], al[2][4];
#pragma unroll
            for (int mt = 0; mt < 2; mt++){
                uint32_t base = aRowOff0 + (uint32_t)(mt << 11);
                ldsm_x4(ah[mt][0], ah[mt][1], ah[mt][2], ah[mt][3],
                        a32 + SWZ(base + hiOff));
                ldsm_x4(al[mt][0], al[mt][1], al[mt][2], al[mt][3],
                        a32 + SWZ(base + loOff));
            }
#pragma unroll
            for (int nt = 0; nt < NTILES; nt++){
                uint32_t b[2];
                ldsm_x2(b[0], b[1], b32 + SWZ(bRowOff + (uint32_t)(nt << 10) + hiOff));
                mma16816(acc[0][nt], ah[0], b);
                mma16816(acc[1][nt], ah[1], b);
                mma16816(acc[0][nt], al[0], b);
                mma16816(acc[1][nt], al[1], b);
            }
#pragma unroll
            for (int nt = 0; nt < NTILES; nt++){
                uint32_t b[2];
                ldsm_x2(b[0], b[1], b32 + SWZ(bRowOff + (uint32_t)(nt << 10) + loOff));
                mma16816(acc[0][nt], ah[0], b);
                mma16816(acc[1][nt], ah[1], b);
            }
        }
        __syncthreads();
    }

    const int r0 = wm * 32 + (lane >> 2);
    const int cc = (lane & 3) * 2;
#pragma unroll
    for (int mt = 0; mt < 2; mt++){
#pragma unroll
        for (int nt = 0; nt < NTILES; nt++){
            const int col = wn * WN + nt * 8 + cc;
            float* p0 = C + (size_t)(r0 + mt * 16) * ldc + col;
            float* p1 = C + (size_t)(r0 + mt * 16 + 8) * ldc + col;
            *reinterpret_cast<float2*>(p0) = make_float2(acc[mt][nt][0], acc[mt][nt][1]);
            *reinterpret_cast<float2*>(p1) = make_float2(acc[mt][nt][2], acc[mt][nt][3]);
        }
    }
}

// ============================ GEMM wrappers (3-combo) =====================
__global__ __launch_bounds__(256)
void k_proj(const __half* __restrict__ Ah, const __half* __restrict__ Al,
            const __half* __restrict__ Bh, const __half* __restrict__ Bl,
            float* __restrict__ C)
{
    size_t ao = (size_t)blockIdx.y * 128 * DM;
    size_t bo = (size_t)blockIdx.x * 128 * DM;
    float* Cp = C + (size_t)blockIdx.y * 128 * DM + blockIdx.x * 128;
    gemm_core<128>(Ah + ao, Al + ao, DM, Bh + bo, Bl + bo, DM, Cp, DM, DM);
}

__global__ __launch_bounds__(256)
void k_proj_cat(const __half* __restrict__ Mh, const __half* __restrict__ Ml,
                const __half* __restrict__ Hh, const __half* __restrict__ Hl,
                const __half* __restrict__ Bh, const __half* __restrict__ Bl,
                float* __restrict__ C)
{
    const int b = blockIdx.z, m0 = blockIdx.y * 128;
    const __half *Ah, *Al;
    if (m0 < ML){ size_t o = ((size_t)b * ML + m0) * DM; Ah = Mh + o; Al = Ml + o; }
    else        { size_t o = ((size_t)b * QL + (m0 - ML)) * DM; Ah = Hh + o; Al = Hl + o; }
    size_t bo = (size_t)blockIdx.x * 128 * DM;
    float* Cp = C + ((size_t)b * KL + m0) * DM + blockIdx.x * 128;
    gemm_core<128>(Ah, Al, DM, Bh + bo, Bl + bo, DM, Cp, DM, DM);
}

// ============= score kernel: Q split x B plain fp16, K=64, 2-combo =======
// A smem: 2 pages (k 0..31 / 32..63) of 128 rows x [32hi|32lo] (32KB).
// B smem: 128 rows x 128B (64 plain fp16 = full K) (16KB).
__global__ __launch_bounds__(256)
void k_score2(const __half* __restrict__ Qh, const __half* __restrict__ Ql,
              const __half* __restrict__ Bp, float* __restrict__ Sout, int kBat)
{
    __shared__ __align__(1024) uint8_t sA[32768];
    __shared__ __align__(1024) uint8_t sB[16384];

    const int tid  = threadIdx.x;
    const int wid  = tid >> 5;
    const int lane = tid & 31;
    const int wm   = wid & 3;
    const int wn   = wid >> 2;

    const int z = blockIdx.z, b = z >> 4, h = z & 15;
    const int i0 = blockIdx.y * 128, j0 = blockIdx.x * 128;
    const int hoff = h * DH;

    const uint32_t a32 = smem_u32(sA), b32 = smem_u32(sB);

    // load A (Q split): 2048 16B segs
    {
        const size_t abase = ((size_t)(b * QL + i0)) * DM + hoff;
#pragma unroll
        for (int i = 0; i < 8; i++){
            int s = tid + (i << 8);
            int pg = s >> 10, rem = s & 1023, row = rem >> 3, j = rem & 7;
            const __half* src = (j < 4)
                ? Qh + abase + (size_t)row * DM + pg * 32 + j * 8
                : Ql + abase + (size_t)row * DM + pg * 32 + (j - 4) * 8;
            uint32_t off = (uint32_t)(pg * 16384) + SWZ((uint32_t)(row << 7) + (uint32_t)(j << 4));
            *reinterpret_cast<uint4*>(sA + off) = *reinterpret_cast<const uint4*>(src);
        }
    }
    // load B (plain fp16 rows of 64): 1024 segs
    {
        const size_t bbase = kBat ? ((size_t)(b * KL + j0)) * DM + hoff
                                  : (size_t)j0 * DM + hoff;
#pragma unroll
        for (int i = 0; i < 4; i++){
            int s = tid + (i << 8);
            int row = s >> 3, j = s & 7;
            const __half* src = Bp + bbase + (size_t)row * DM + j * 8;
            uint32_t off = SWZ((uint32_t)(row << 7) + (uint32_t)(j << 4));
            *reinterpret_cast<uint4*>(sB + off) = *reinterpret_cast<const uint4*>(src);
        }
    }
    __syncthreads();

    float acc[2][8][4];
#pragma unroll
    for (int mt = 0; mt < 2; mt++)
#pragma unroll
        for (int nt = 0; nt < 8; nt++)
#pragma unroll
            for (int q = 0; q < 4; q++) acc[mt][nt][q] = 0.0f;

    const uint32_t aRowOff0 = (uint32_t)((wm * 32 + (lane & 15)) << 7) + ((lane >> 4) << 4);
    const uint32_t bRowOff  = (uint32_t)((wn * 64 + (lane & 7)) << 7) + (((lane >> 3) & 1) << 4);

#pragma unroll
    for (int s16 = 0; s16 < 4; s16++){
        const uint32_t apg = (uint32_t)(s16 >> 1) * 16384u;
        const uint32_t hiOff = (uint32_t)((s16 & 1) << 5);
        const uint32_t bOff  = (uint32_t)(s16 << 5);

        uint32_t ah[2][4], al[2][4];
#pragma unroll
        for (int mt = 0; mt < 2; mt++){
            uint32_t base = aRowOff0 + (uint32_t)(mt << 11);
            ldsm_x4(ah[mt][0], ah[mt][1], ah[mt][2], ah[mt][3],
                    a32 + apg + SWZ(base + hiOff));
            ldsm_x4(al[mt][0], al[mt][1], al[mt][2], al[mt][3],
                    a32 + apg + SWZ(base + hiOff + 64));
        }
#pragma unroll
        for (int nt = 0; nt < 8; nt++){
            uint32_t bb[2];
            ldsm_x2(bb[0], bb[1], b32 + SWZ(bRowOff + (uint32_t)(nt << 10) + bOff));
            mma16816(acc[0][nt], ah[0], bb);
            mma16816(acc[1][nt], ah[1], bb);
            mma16816(acc[0][nt], al[0], bb);
            mma16816(acc[1][nt], al[1], bb);
        }
    }

    float* Cp = Sout + ((size_t)z * QL + i0) * KL + j0;
    const int r0 = wm * 32 + (lane >> 2);
    const int cc = (lane & 3) * 2;
#pragma unroll
    for (int mt = 0; mt < 2; mt++){
#pragma unroll
        for (int nt = 0; nt < 8; nt++){
            const int col = wn * 64 + nt * 8 + cc;
            float* p0 = Cp + (size_t)(r0 + mt * 16) * KL + col;
            float* p1 = Cp + (size_t)(r0 + mt * 16 + 8) * KL + col;
            *reinterpret_cast<float2*>(p0) = make_float2(acc[mt][nt][0], acc[mt][nt][1]);
            *reinterpret_cast<float2*>(p1) = make_float2(acc[mt][nt][2], acc[mt][nt][3]);
        }
    }
}

// ============= av kernel: P plain fp16 x VT split, 2-combo, K=2048 =======
// A smem: 128 rows x 128B (64 plain fp16 per chunk).  B smem: 2 pages of
// 64 rows x [32hi|32lo].  Register prefetch, single buffer.
__global__ __launch_bounds__(256)
void k_av2(const __half* __restrict__ P, const __half* __restrict__ VTh,
           const __half* __restrict__ VTl, float* __restrict__ AV)
{
    __shared__ __align__(1024) uint8_t sA[16384];
    __shared__ __align__(1024) uint8_t sB[16384];

    const int tid  = threadIdx.x;
    const int wid  = tid >> 5;
    const int lane = tid & 31;
    const int wm   = wid & 3;
    const int wn   = wid >> 2;

    const int z = blockIdx.z, b = z >> 4, h = z & 15;
    const int i0 = blockIdx.y * 128;
    const size_t prow = (size_t)z * QL + i0;
    const size_t vrow = (size_t)b * DM + h * DH;

    const uint32_t a32 = smem_u32(sA), b32 = smem_u32(sB);

    float acc[2][4][4];
#pragma unroll
    for (int mt = 0; mt < 2; mt++)
#pragma unroll
        for (int nt = 0; nt < 4; nt++)
#pragma unroll
            for (int q = 0; q < 4; q++) acc[mt][nt][q] = 0.0f;

    uint4 pa[4], pb[4];
    auto ldg_chunk = [&](int k0){
#pragma unroll
        for (int i = 0; i < 4; i++){
            int s = tid + (i << 8); int row = s >> 3, j = s & 7;
            pa[i] = *reinterpret_cast<const uint4*>(P + (prow + row) * KL + k0 + j * 8);
        }
#pragma unroll
        for (int i = 0; i < 4; i++){
            int s = tid + (i << 8);
            int pg = s >> 9, rem = s & 511, row = rem >> 3, j = rem & 7;
            const __half* src = (j < 4)
                ? VTh + (vrow + row) * KL + k0 + pg * 32 + j * 8
                : VTl + (vrow + row) * KL + k0 + pg * 32 + (j - 4) * 8;
            pb[i] = *reinterpret_cast<const uint4*>(src);
        }
    };

    const uint32_t aRowOff0 = (uint32_t)((wm * 32 + (lane & 15)) << 7) + ((lane >> 4) << 4);
    const uint32_t bRowOff  = (uint32_t)((wn * 32 + (lane & 7)) << 7) + (((lane >> 3) & 1) << 4);

    ldg_chunk(0);

    for (int c = 0; c < KL / 64; c++){
#pragma unroll
        for (int i = 0; i < 4; i++){
            int s = tid + (i << 8);
            uint32_t off = SWZ((uint32_t)((s >> 3) << 7) + (uint32_t)((s & 7) << 4));
            *reinterpret_cast<uint4*>(sA + off) = pa[i];
        }
#pragma unroll
        for (int i = 0; i < 4; i++){
            int s = tid + (i << 8);
            int pg = s >> 9, rem = s & 511;
            uint32_t off = (uint32_t)(pg * 8192)
                         + SWZ((uint32_t)((rem >> 3) << 7) + (uint32_t)((rem & 7) << 4));
            *reinterpret_cast<uint4*>(sB + off) = pb[i];
        }
        __syncthreads();

        if (c + 1 < KL / 64) ldg_chunk((c + 1) << 6);

#pragma unroll
        for (int s16 = 0; s16 < 4; s16++){
            const uint32_t aOff  = (uint32_t)(s16 << 5);
            const uint32_t bpg   = (uint32_t)(s16 >> 1) * 8192u;
            const uint32_t hiOff = (uint32_t)((s16 & 1) << 5);

            uint32_t av[2][4];
#pragma unroll
            for (int mt = 0; mt < 2; mt++){
                uint32_t base = aRowOff0 + (uint32_t)(mt << 11);
                ldsm_x4(av[mt][0], av[mt][1], av[mt][2], av[mt][3],
                        a32 + SWZ(base + aOff));
            }
#pragma unroll
            for (int nt = 0; nt < 4; nt++){
                uint32_t bh[2], bl[2];
                ldsm_x2(bh[0], bh[1], b32 + bpg + SWZ(bRowOff + (uint32_t)(nt << 10) + hiOff));
                mma16816(acc[0][nt], av[0], bh);
                mma16816(acc[1][nt], av[1], bh);
                ldsm_x2(bl[0], bl[1], b32 + bpg + SWZ(bRowOff + (uint32_t)(nt << 10) + hiOff + 64));
                mma16816(acc[0][nt], av[0], bl);
                mma16816(acc[1][nt], av[1], bl);
            }
        }
        __syncthreads();
    }

    float* Cp = AV + ((size_t)(b * QL + i0)) * DM + h * DH;
    const int r0 = wm * 32 + (lane >> 2);
    const int cc = (lane & 3) * 2;
#pragma unroll
    for (int mt = 0; mt < 2; mt++){
#pragma unroll
        for (int nt = 0; nt < 4; nt++){
            const int col = wn * 32 + nt * 8 + cc;
            float* p0 = Cp + (size_t)(r0 + mt * 16) * DM + col;
            float* p1 = Cp + (size_t)(r0 + mt * 16 + 8) * DM + col;
            *reinterpret_cast<float2*>(p0) = make_float2(acc[mt][nt][0], acc[mt][nt][1]);
            *reinterpret_cast<float2*>(p1) = make_float2(acc[mt][nt][2], acc[mt][nt][3]);
        }
    }
}

// ============================ conversions =================================
__device__ __forceinline__ void split1(float x, __half& h, __half& l){
    h = __float2half(x);
    l = __float2half(x - __half2float(h));
}

__global__ __launch_bounds__(256)
void k_split(const float* __restrict__ x, __half* __restrict__ h,
             __half* __restrict__ l, size_t n)
{
    size_t i = ((size_t)blockIdx.x * 256 + threadIdx.x) * 4;
    if (i >= n) return;
    float4 v = *reinterpret_cast<const float4*>(x + i);
    __half h0, h1, h2, h3, l0, l1, l2, l3;
    split1(v.x, h0, l0); split1(v.y, h1, l1);
    split1(v.z, h2, l2); split1(v.w, h3, l3);
    *reinterpret_cast<__half2*>(h + i)     = __halves2half2(h0, h1);
    *reinterpret_cast<__half2*>(h + i + 2) = __halves2half2(h2, h3);
    *reinterpret_cast<__half2*>(l + i)     = __halves2half2(l0, l1);
    *reinterpret_cast<__half2*>(l + i + 2) = __halves2half2(l2, l3);
}

__global__ __launch_bounds__(256)
void k_tofp16(const float* __restrict__ x, __half* __restrict__ o, size_t n)
{
    size_t i = ((size_t)blockIdx.x * 256 + threadIdx.x) * 4;
    if (i >= n) return;
    float4 v = *reinterpret_cast<const float4*>(x + i);
    *reinterpret_cast<__half2*>(o + i)     = __halves2half2(__float2half(v.x), __float2half(v.y));
    *reinterpret_cast<__half2*>(o + i + 2) = __halves2half2(__float2half(v.z), __float2half(v.w));
}

__global__ __launch_bounds__(256)
void k_split_qbias(const float* __restrict__ q,
                   const float* __restrict__ b1, const float* __restrict__ b2,
                   __half* __restrict__ h1, __half* __restrict__ l1,
                   __half* __restrict__ h2, __half* __restrict__ l2,
                   size_t n)
{
    size_t i = ((size_t)blockIdx.x * 256 + threadIdx.x) * 4;
    if (i >= n) return;
    const int col = (int)(i & (DM - 1));
    float4 v = *reinterpret_cast<const float4*>(q + i);
    float4 a = *reinterpret_cast<const float4*>(b1 + col);
    float4 c = *reinterpret_cast<const float4*>(b2 + col);
    __half h0, h1b, h2b, h3, l0, l1b, l2b, l3;
    split1(v.x + a.x, h0, l0);  split1(v.y + a.y, h1b, l1b);
    split1(v.z + a.z, h2b, l2b); split1(v.w + a.w, h3, l3);
    *reinterpret_cast<__half2*>(h1 + i)     = __halves2half2(h0, h1b);
    *reinterpret_cast<__half2*>(h1 + i + 2) = __halves2half2(h2b, h3);
    *reinterpret_cast<__half2*>(l1 + i)     = __halves2half2(l0, l1b);
    *reinterpret_cast<__half2*>(l1 + i + 2) = __halves2half2(l2b, l3);
    split1(v.x + c.x, h0, l0);  split1(v.y + c.y, h1b, l1b);
    split1(v.z + c.z, h2b, l2b); split1(v.w + c.w, h3, l3);
    *reinterpret_cast<__half2*>(h2 + i)     = __halves2half2(h0, h1b);
    *reinterpret_cast<__half2*>(h2 + i + 2) = __halves2half2(h2b, h3);
    *reinterpret_cast<__half2*>(l2 + i)     = __halves2half2(l0, l1b);
    *reinterpret_cast<__half2*>(l2 + i + 2) = __halves2half2(l2b, l3);
}

// out[b][c][r] = split(x[b][r][c]) ; grid (C/32, R/32, batch), block (32,8)
__global__ __launch_bounds__(256)
void k_tsplit(const float* __restrict__ x, __half* __restrict__ th,
              __half* __restrict__ tl, int R, int C)
{
    __shared__ float t[32][33];
    const int bz = blockIdx.z;
    const float* xb = x + (size_t)bz * R * C;
    __half* ph = th + (size_t)bz * R * C;
    __half* pl = tl + (size_t)bz * R * C;
    const int c0 = blockIdx.x * 32, r0 = blockIdx.y * 32;
    const int tx = threadIdx.x, ty = threadIdx.y;
    for (int i = ty; i < 32; i += 8)
        t[i][tx] = xb[(size_t)(r0 + i) * C + c0 + tx];
    __syncthreads();
    for (int i = ty; i < 32; i += 8){
        __half h, l; split1(t[tx][i], h, l);
        ph[(size_t)(c0 + i) * R + r0 + tx] = h;
        pl[(size_t)(c0 + i) * R + r0 + tx] = l;
    }
}

// ============================ softmax =====================================
__global__ __launch_bounds__(256)
void k_softmax(const float* __restrict__ S, const float* __restrict__ BD,
               __half* __restrict__ Pp)
{
    const int row = blockIdx.x;
    const int i   = row & (QL - 1);
    const float* srow = S + (size_t)row * KL;
    const float* x0 = BD + (size_t)row * KL;
    const float* x1 = x0 + KL;

    const int tid = threadIdx.x, lane = tid & 31, warp = tid >> 5;
    __shared__ float red[8];

    float sc[8];
    float mx = -1e30f;
#pragma unroll
    for (int c = 0; c < 8; c++){
        const int j = c * 256 + tid;
        const int d = j - i;
        float bdv;
        if (d <= QL)           bdv = x0[j - i + (QL - 1)];
        else if (d == QL + 1)  bdv = 0.0f;
        else                   bdv = x1[j - i - (QL + 2)];
        const float v = (srow[j] + bdv) * 0.125f;
        sc[c] = v;
        mx = fmaxf(mx, v);
    }
#pragma unroll
    for (int o = 16; o > 0; o >>= 1) mx = fmaxf(mx, __shfl_xor_sync(0xffffffffu, mx, o));
    if (lane == 0) red[warp] = mx;
    __syncthreads();
    float rowmax = red[0];
#pragma unroll
    for (int w = 1; w < 8; w++) rowmax = fmaxf(rowmax, red[w]);
    __syncthreads();

    float sum = 0.0f;
#pragma unroll
    for (int c = 0; c < 8; c++){ sc[c] = __expf(sc[c] - rowmax); sum += sc[c]; }
#pragma unroll
    for (int o = 16; o > 0; o >>= 1) sum += __shfl_xor_sync(0xffffffffu, sum, o);
    if (lane == 0) red[warp] = sum;
    __syncthreads();
    float rowsum = 0.0f;
#pragma unroll
    for (int w = 0; w < 8; w++) rowsum += red[w];
    const float inv = 1.0f / rowsum;

    __half* ph = Pp + (size_t)row * KL;
#pragma unroll
    for (int c = 0; c < 8; c++){
        const int j = c * 256 + tid;
        ph[j] = __float2half(sc[c] * inv);
    }
}

// ============================ launch ======================================
extern "C" void kernel_launch(void* const* d_in, const int* in_sizes, int n_in,
                              void* d_out, int out_size)
{
    const float* h_in  = (const float*)d_in[0];
    const float* mem_p = (const float*)d_in[1];
    const float* r_p   = (const float*)d_in[2];
    const float* W[5]  = { (const float*)d_in[3], (const float*)d_in[4],
                           (const float*)d_in[5], (const float*)d_in[6],
                           (const float*)d_in[7] };   // Wq, Wk, Wv, Wr, Wo
    const float* rwb   = (const float*)d_in[8];
    const float* rrb   = (const float*)d_in[9];
    float* out = (float*)d_out;

    __half* hf; float* fp;
    cudaGetSymbolAddress((void**)&hf, g_hf);
    cudaGetSymbolAddress((void**)&fp, g_f);

    // 1) split inputs (fp16)
    k_split<<<2048, 256>>>(h_in,  hf + oHSPh, hf + oHSPl, SZ_2M);
    k_split<<<2048, 256>>>(mem_p, hf + oMSPh, hf + oMSPl, SZ_2M);
    k_split<<<2048, 256>>>(r_p,   hf + oRSPh, hf + oRSPl, SZ_2M);

    // 2) transpose+split weights: Wt[n][k]
    for (int w = 0; w < 5; w++){
        __half* th = hf + oWT + (size_t)w * 2 * SZ_1M;
        k_tsplit<<<dim3(32, 32, 1), dim3(32, 8)>>>(W[w], th, th + SZ_1M, 1024, 1024);
    }
    const __half *wq = hf + oWT,            *wk = hf + oWT + 2 * SZ_1M,
                 *wv = hf + oWT + 4 * SZ_1M, *wr = hf + oWT + 6 * SZ_1M,
                 *wo = hf + oWT + 8 * SZ_1M;

    // 3) projections (3-combo fp16)
    k_proj<<<dim3(8, 16), 256>>>(hf + oHSPh, hf + oHSPl, wq, wq + SZ_1M, fp + fQ);
    k_proj_cat<<<dim3(8, 16, 2), 256>>>(hf + oMSPh, hf + oMSPl, hf + oHSPh, hf + oHSPl,
                                        wk, wk + SZ_1M, fp + fK);
    k_proj_cat<<<dim3(8, 16, 2), 256>>>(hf + oMSPh, hf + oMSPl, hf + oHSPh, hf + oHSPl,
                                        wv, wv + SZ_1M, fp + fV);
    k_proj<<<dim3(8, 16), 256>>>(hf + oRSPh, hf + oRSPl, wr, wr + SZ_1M, fp + fR);

    // 4) post-proj conversions
    k_split_qbias<<<2048, 256>>>(fp + fQ, rwb, rrb,
                                 hf + oQWh, hf + oQWl, hf + oQRh, hf + oQRl, SZ_2M);
    k_tofp16<<<4096, 256>>>(fp + fK, hf + oKp,  SZ_4M);   // K plain fp16
    k_tofp16<<<2048, 256>>>(fp + fR, hf + oRHp, SZ_2M);   // R plain fp16
    k_tsplit<<<dim3(32, 64, 2), dim3(32, 8)>>>(fp + fV, hf + oVTh, hf + oVTl, KL, DM);

    // 5) scores: 2-combo fp16 (Q split x plain B)
    k_score2<<<dim3(16, 8, 32), 256>>>(hf + oQWh, hf + oQWl, hf + oKp,  fp + fS, 1);
    k_score2<<<dim3(16, 8, 32), 256>>>(hf + oQRh, hf + oQRl, hf + oRHp, fp + fBD, 0);

    // 6) fused rel_shift + softmax -> plain fp16 probs
    k_softmax<<<B_SZ * NH * QL, 256>>>(fp + fS, fp + fBD, hf + oPp);

    // 7) attn_vec = prob @ v (2-combo: P plain x V split)
    k_av2<<<dim3(1, 8, 32), 256>>>(hf + oPp, hf + oVTh, hf + oVTl, fp + fAV);

    // 8) out = attn_vec @ Wo (3-combo)
    k_split<<<2048, 256>>>(fp + fAV, hf + oAVh, hf + oAVl, SZ_2M);
    k_proj<<<dim3(8, 16), 256>>>(hf + oAVh, hf + oAVl, wo, wo + SZ_1M, out);
}

// round 10
// speedup vs baseline: 3.0763x; 1.1434x over previous
#include <cuda_runtime.h>
#include <cuda_fp16.h>
#include <cstdint>
#include <cstddef>

#define B_SZ 2
#define QL   1024
#define ML   1024
#define KL   2048
#define DM   1024
#define NH   16
#define DH   64

// ============================ helpers =====================================
__device__ __forceinline__ uint32_t smem_u32(const void* p){
    uint32_t a;
    asm("{ .reg .u64 t; cvta.to.shared.u64 t, %1; cvt.u32.u64 %0, t; }" : "=r"(a) : "l"(p));
    return a;
}

#define SWZ(o) ((o) ^ (((o) >> 3) & 0x70))

__device__ __forceinline__ void ldsm_x4(uint32_t& r0, uint32_t& r1, uint32_t& r2,
                                        uint32_t& r3, uint32_t a){
    asm volatile("ldmatrix.sync.aligned.m8n8.x4.shared.b16 {%0,%1,%2,%3},[%4];"
                 : "=r"(r0), "=r"(r1), "=r"(r2), "=r"(r3) : "r"(a));
}
__device__ __forceinline__ void ldsm_x2(uint32_t& r0, uint32_t& r1, uint32_t a){
    asm volatile("ldmatrix.sync.aligned.m8n8.x2.shared.b16 {%0,%1},[%2];"
                 : "=r"(r0), "=r"(r1) : "r"(a));
}
// fp16 MMA, fp32 accumulate
__device__ __forceinline__ void mma16816(float* c, const uint32_t* a, const uint32_t* b){
    asm volatile(
        "mma.sync.aligned.m16n8k16.row.col.f32.f16.f16.f32 "
        "{%0,%1,%2,%3},{%4,%5,%6,%7},{%8,%9},{%0,%1,%2,%3};"
        : "+f"(c[0]), "+f"(c[1]), "+f"(c[2]), "+f"(c[3])
        : "r"(a[0]), "r"(a[1]), "r"(a[2]), "r"(a[3]), "r"(b[0]), "r"(b[1]));
}

// ============================ scratch pools ===============================
#define SZ_1M ((size_t)1024 * 1024)
#define SZ_2M ((size_t)2048 * 1024)
#define SZ_4M ((size_t)4096 * 1024)
#define SZ_P  ((size_t)B_SZ * NH * QL * KL)

constexpr size_t oHSPh = 0,               oHSPl = oHSPh + SZ_2M;
constexpr size_t oMSPh = oHSPl + SZ_2M,   oMSPl = oMSPh + SZ_2M;
constexpr size_t oRSPh = oMSPl + SZ_2M,   oRSPl = oRSPh + SZ_2M;
constexpr size_t oWT   = oRSPl + SZ_2M;                       // 5 x (hi 1M | lo 1M)
constexpr size_t oQWh  = oWT + 10 * SZ_1M, oQWl = oQWh + SZ_2M;
constexpr size_t oQRh  = oQWl + SZ_2M,    oQRl = oQRh + SZ_2M;
constexpr size_t oKp   = oQRl + SZ_2M;                        // K plain fp16 (4M)
constexpr size_t oRHp  = oKp + SZ_4M;                         // R plain fp16 (2M)
constexpr size_t oVTh  = oRHp + SZ_2M,    oVTl = oVTh + SZ_4M;
constexpr size_t oPp   = oVTl + SZ_4M;                        // P plain fp16 (64M)
constexpr size_t oAVh  = oPp + SZ_P,      oAVl = oAVh + SZ_2M;
constexpr size_t HF_TOTAL = oAVl + SZ_2M;

constexpr size_t fQ  = 0;
constexpr size_t fV  = fQ + SZ_2M;
constexpr size_t fAV = fV + SZ_4M;
constexpr size_t fS  = fAV + SZ_2M;
constexpr size_t fBD = fS + SZ_P;
constexpr size_t F_TOTAL = fBD + SZ_P;

__device__ __half g_hf[HF_TOTAL];
__device__ float  g_f [F_TOTAL];

// ============================ GEMM core (3-combo, split x split) ==========
// Used only for the Q projection (accuracy anchor).
template <int NT>
__device__ __forceinline__ void gemm_core(
    const __half* __restrict__ Ahi, const __half* __restrict__ Alo, int lda,
    const __half* __restrict__ Bhi, const __half* __restrict__ Blo, int ldb,
    float* __restrict__ C, int ldc, int K)
{
    __shared__ __align__(1024) uint8_t sA[128 * 128];
    __shared__ __align__(1024) uint8_t sB[NT * 128];

    const int tid  = threadIdx.x;
    const int wid  = tid >> 5;
    const int lane = tid & 31;
    const int wm   = wid & 3;
    const int wn   = wid >> 2;
    constexpr int WN     = NT / 2;
    constexpr int NTILES = WN / 8;
    constexpr int BSEG   = NT / 32;

    const uint32_t a32 = smem_u32(sA), b32 = smem_u32(sB);

    float acc[2][NTILES][4];
#pragma unroll
    for (int mt = 0; mt < 2; mt++)
#pragma unroll
        for (int nt = 0; nt < NTILES; nt++)
#pragma unroll
            for (int q = 0; q < 4; q++) acc[mt][nt][q] = 0.0f;

    uint4 pa[4], pb[BSEG];
    const int nch = K >> 5;

    auto ldg_chunk = [&](int k0){
#pragma unroll
        for (int i = 0; i < 4; i++){
            int s = tid + (i << 8); int row = s >> 3, j = s & 7;
            const __half* p = (j < 4)
                ? Ahi + (size_t)row * lda + k0 + j * 8
                : Alo + (size_t)row * lda + k0 + (j - 4) * 8;
            pa[i] = *reinterpret_cast<const uint4*>(p);
        }
#pragma unroll
        for (int i = 0; i < BSEG; i++){
            int s = tid + (i << 8); int row = s >> 3, j = s & 7;
            const __half* p = (j < 4)
                ? Bhi + (size_t)row * ldb + k0 + j * 8
                : Blo + (size_t)row * ldb + k0 + (j - 4) * 8;
            pb[i] = *reinterpret_cast<const uint4*>(p);
        }
    };

    const uint32_t aRowOff0 = (uint32_t)((wm * 32 + (lane & 15)) << 7) + ((lane >> 4) << 4);
    const uint32_t bRowOff  = (uint32_t)((wn * WN + (lane & 7)) << 7) + (((lane >> 3) & 1) << 4);

    ldg_chunk(0);

    for (int c = 0; c < nch; c++){
#pragma unroll
        for (int i = 0; i < 4; i++){
            int s = tid + (i << 8);
            uint32_t off = (uint32_t)((s >> 3) << 7) + (uint32_t)((s & 7) << 4);
            *reinterpret_cast<uint4*>(sA + SWZ(off)) = pa[i];
        }
#pragma unroll
        for (int i = 0; i < BSEG; i++){
            int s = tid + (i << 8);
            uint32_t off = (uint32_t)((s >> 3) << 7) + (uint32_t)((s & 7) << 4);
            *reinterpret_cast<uint4*>(sB + SWZ(off)) = pb[i];
        }
        __syncthreads();

        if (c + 1 < nch) ldg_chunk((c + 1) << 5);

#pragma unroll
        for (int kh = 0; kh < 2; kh++){
            const uint32_t hiOff = (uint32_t)(kh << 5);
            const uint32_t loOff = hiOff + 64;

            uint32_t ah[2][4], al[2][4];
#pragma unroll
            for (int mt = 0; mt < 2; mt++){
                uint32_t base = aRowOff0 + (uint32_t)(mt << 11);
                ldsm_x4(ah[mt][0], ah[mt][1], ah[mt][2], ah[mt][3],
                        a32 + SWZ(base + hiOff));
                ldsm_x4(al[mt][0], al[mt][1], al[mt][2], al[mt][3],
                        a32 + SWZ(base + loOff));
            }
#pragma unroll
            for (int nt = 0; nt < NTILES; nt++){
                uint32_t b[2];
                ldsm_x2(b[0], b[1], b32 + SWZ(bRowOff + (uint32_t)(nt << 10) + hiOff));
                mma16816(acc[0][nt], ah[0], b);
                mma16816(acc[1][nt], ah[1], b);
                mma16816(acc[0][nt], al[0], b);
                mma16816(acc[1][nt], al[1], b);
            }
#pragma unroll
            for (int nt = 0; nt < NTILES; nt++){
                uint32_t b[2];
                ldsm_x2(b[0], b[1], b32 + SWZ(bRowOff + (uint32_t)(nt << 10) + loOff));
                mma16816(acc[0][nt], ah[0], b);
                mma16816(acc[1][nt], ah[1], b);
            }
        }
        __syncthreads();
    }

    const int r0 = wm * 32 + (lane >> 2);
    const int cc = (lane & 3) * 2;
#pragma unroll
    for (int mt = 0; mt < 2; mt++){
#pragma unroll
        for (int nt = 0; nt < NTILES; nt++){
            const int col = wn * WN + nt * 8 + cc;
            float* p0 = C + (size_t)(r0 + mt * 16) * ldc + col;
            float* p1 = C + (size_t)(r0 + mt * 16 + 8) * ldc + col;
            *reinterpret_cast<float2*>(p0) = make_float2(acc[mt][nt][0], acc[mt][nt][1]);
            *reinterpret_cast<float2*>(p1) = make_float2(acc[mt][nt][2], acc[mt][nt][3]);
        }
    }
}

// ============================ GEMM core (2-combo, split x plain) ==========
// C[128, NT] = (Ahi+Alo)[128,K] * Bp[NT,K]^T.
// A smem: 128 rows x [32hi|32lo] per 32-K chunk (16KB, single buffer).
// B smem: NT rows x 128B (64 plain fp16 = a 64-K pair), double-buffered.
// OUT16: write __half instead of float.
template <int NT, bool OUT16>
__device__ __forceinline__ void gemm2_core(
    const __half* __restrict__ Ahi, const __half* __restrict__ Alo, int lda,
    const __half* __restrict__ Bp, int ldb,
    void* __restrict__ Cv, int ldc, int K)
{
    __shared__ __align__(1024) uint8_t sA[16384];
    __shared__ __align__(1024) uint8_t sB[2][NT * 128];

    const int tid  = threadIdx.x;
    const int wid  = tid >> 5;
    const int lane = tid & 31;
    const int wm   = wid & 3;
    const int wn   = wid >> 2;
    constexpr int WN     = NT / 2;
    constexpr int NTILES = WN / 8;
    constexpr int BSEG   = NT / 32;    // 16B segs per thread for one B page

    const uint32_t a32 = smem_u32(sA), b32 = smem_u32(&sB[0][0]);
    constexpr uint32_t BSTRIDE = (uint32_t)NT * 128;

    float acc[2][NTILES][4];
#pragma unroll
    for (int mt = 0; mt < 2; mt++)
#pragma unroll
        for (int nt = 0; nt < NTILES; nt++)
#pragma unroll
            for (int q = 0; q < 4; q++) acc[mt][nt][q] = 0.0f;

    uint4 pa[4], pb[BSEG];
    const int nch = K >> 5;

    auto ldgA = [&](int k0){
#pragma unroll
        for (int i = 0; i < 4; i++){
            int s = tid + (i << 8); int row = s >> 3, j = s & 7;
            const __half* p = (j < 4)
                ? Ahi + (size_t)row * lda + k0 + j * 8
                : Alo + (size_t)row * lda + k0 + (j - 4) * 8;
            pa[i] = *reinterpret_cast<const uint4*>(p);
        }
    };
    auto ldgB = [&](int k0){   // loads a full 64-wide pair
#pragma unroll
        for (int i = 0; i < BSEG; i++){
            int s = tid + (i << 8); int row = s >> 3, j = s & 7;
            pb[i] = *reinterpret_cast<const uint4*>(Bp + (size_t)row * ldb + k0 + j * 8);
        }
    };

    const uint32_t aRowOff0 = (uint32_t)((wm * 32 + (lane & 15)) << 7) + ((lane >> 4) << 4);
    const uint32_t bRowOff  = (uint32_t)((wn * WN + (lane & 7)) << 7) + (((lane >> 3) & 1) << 4);

    ldgA(0);
    ldgB(0);

    for (int c = 0; c < nch; c++){
        // store A chunk
#pragma unroll
        for (int i = 0; i < 4; i++){
            int s = tid + (i << 8);
            uint32_t off = (uint32_t)((s >> 3) << 7) + (uint32_t)((s & 7) << 4);
            *reinterpret_cast<uint4*>(sA + SWZ(off)) = pa[i];
        }
        // store B pair at even c
        if ((c & 1) == 0){
            uint8_t* dst = &sB[(c >> 1) & 1][0];
#pragma unroll
            for (int i = 0; i < BSEG; i++){
                int s = tid + (i << 8);
                uint32_t off = (uint32_t)((s >> 3) << 7) + (uint32_t)((s & 7) << 4);
                *reinterpret_cast<uint4*>(dst + SWZ(off)) = pb[i];
            }
        }
        __syncthreads();

        if (c + 1 < nch) ldgA((c + 1) << 5);
        if ((c & 1) == 1){
            int nk0 = ((c >> 1) + 1) << 6;
            if (nk0 < K) ldgB(nk0);
        }

        const uint32_t bb = b32 + (uint32_t)((c >> 1) & 1) * BSTRIDE;
        const uint32_t bCol = (uint32_t)((c & 1) << 6);   // 0 or 64 bytes

#pragma unroll
        for (int kh = 0; kh < 2; kh++){
            const uint32_t hiOff = (uint32_t)(kh << 5);
            const uint32_t bOff  = bCol + hiOff;

            uint32_t ah[2][4], al[2][4];
#pragma unroll
            for (int mt = 0; mt < 2; mt++){
                uint32_t base = aRowOff0 + (uint32_t)(mt << 11);
                ldsm_x4(ah[mt][0], ah[mt][1], ah[mt][2], ah[mt][3],
                        a32 + SWZ(base + hiOff));
                ldsm_x4(al[mt][0], al[mt][1], al[mt][2], al[mt][3],
                        a32 + SWZ(base + hiOff + 64));
            }
#pragma unroll
            for (int nt = 0; nt < NTILES; nt++){
                uint32_t b[2];
                ldsm_x2(b[0], b[1], bb + SWZ(bRowOff + (uint32_t)(nt << 10) + bOff));
                mma16816(acc[0][nt], ah[0], b);
                mma16816(acc[1][nt], ah[1], b);
                mma16816(acc[0][nt], al[0], b);
                mma16816(acc[1][nt], al[1], b);
            }
        }
        __syncthreads();
    }

    const int r0 = wm * 32 + (lane >> 2);
    const int cc = (lane & 3) * 2;
    if (OUT16){
        __half* Ch = reinterpret_cast<__half*>(Cv);
#pragma unroll
        for (int mt = 0; mt < 2; mt++){
#pragma unroll
            for (int nt = 0; nt < NTILES; nt++){
                const int col = wn * WN + nt * 8 + cc;
                __half2 v0 = __floats2half2_rn(acc[mt][nt][0], acc[mt][nt][1]);
                __half2 v1 = __floats2half2_rn(acc[mt][nt][2], acc[mt][nt][3]);
                *reinterpret_cast<__half2*>(Ch + (size_t)(r0 + mt * 16) * ldc + col)     = v0;
                *reinterpret_cast<__half2*>(Ch + (size_t)(r0 + mt * 16 + 8) * ldc + col) = v1;
            }
        }
    } else {
        float* C = reinterpret_cast<float*>(Cv);
#pragma unroll
        for (int mt = 0; mt < 2; mt++){
#pragma unroll
            for (int nt = 0; nt < NTILES; nt++){
                const int col = wn * WN + nt * 8 + cc;
                float* p0 = C + (size_t)(r0 + mt * 16) * ldc + col;
                float* p1 = C + (size_t)(r0 + mt * 16 + 8) * ldc + col;
                *reinterpret_cast<float2*>(p0) = make_float2(acc[mt][nt][0], acc[mt][nt][1]);
                *reinterpret_cast<float2*>(p1) = make_float2(acc[mt][nt][2], acc[mt][nt][3]);
            }
        }
    }
}

// ============================ GEMM wrappers ===============================
// Q projection: 3-combo (accuracy anchor)
__global__ __launch_bounds__(256)
void k_proj(const __half* __restrict__ Ah, const __half* __restrict__ Al,
            const __half* __restrict__ Bh, const __half* __restrict__ Bl,
            float* __restrict__ C)
{
    size_t ao = (size_t)blockIdx.y * 128 * DM;
    size_t bo = (size_t)blockIdx.x * 128 * DM;
    float* Cp = C + (size_t)blockIdx.y * 128 * DM + blockIdx.x * 128;
    gemm_core<128>(Ah + ao, Al + ao, DM, Bh + bo, Bl + bo, DM, Cp, DM, DM);
}

// R projection: 2-combo, fp16 out
__global__ __launch_bounds__(256)
void k_proj2_f16(const __half* __restrict__ Ah, const __half* __restrict__ Al,
                 const __half* __restrict__ Bp, __half* __restrict__ C)
{
    size_t ao = (size_t)blockIdx.y * 128 * DM;
    size_t bo = (size_t)blockIdx.x * 128 * DM;
    __half* Cp = C + (size_t)blockIdx.y * 128 * DM + blockIdx.x * 128;
    gemm2_core<128, true>(Ah + ao, Al + ao, DM, Bp + bo, DM, Cp, DM, DM);
}

// out projection: 2-combo, fp32 out
__global__ __launch_bounds__(256)
void k_proj2_f32(const __half* __restrict__ Ah, const __half* __restrict__ Al,
                 const __half* __restrict__ Bp, float* __restrict__ C)
{
    size_t ao = (size_t)blockIdx.y * 128 * DM;
    size_t bo = (size_t)blockIdx.x * 128 * DM;
    float* Cp = C + (size_t)blockIdx.y * 128 * DM + blockIdx.x * 128;
    gemm2_core<128, false>(Ah + ao, Al + ao, DM, Bp + bo, DM, Cp, DM, DM);
}

// K projection: 2-combo over cat, fp16 out
__global__ __launch_bounds__(256)
void k_projcat2_f16(const __half* __restrict__ Mh, const __half* __restrict__ Ml,
                    const __half* __restrict__ Hh, const __half* __restrict__ Hl,
                    const __half* __restrict__ Bp, __half* __restrict__ C)
{
    const int b = blockIdx.z, m0 = blockIdx.y * 128;
    const __half *Ah, *Al;
    if (m0 < ML){ size_t o = ((size_t)b * ML + m0) * DM; Ah = Mh + o; Al = Ml + o; }
    else        { size_t o = ((size_t)b * QL + (m0 - ML)) * DM; Ah = Hh + o; Al = Hl + o; }
    size_t bo = (size_t)blockIdx.x * 128 * DM;
    __half* Cp = C + ((size_t)b * KL + m0) * DM + blockIdx.x * 128;
    gemm2_core<128, true>(Ah, Al, DM, Bp + bo, DM, Cp, DM, DM);
}

// V projection: 2-combo over cat, fp32 out
__global__ __launch_bounds__(256)
void k_projcat2_f32(const __half* __restrict__ Mh, const __half* __restrict__ Ml,
                    const __half* __restrict__ Hh, const __half* __restrict__ Hl,
                    const __half* __restrict__ Bp, float* __restrict__ C)
{
    const int b = blockIdx.z, m0 = blockIdx.y * 128;
    const __half *Ah, *Al;
    if (m0 < ML){ size_t o = ((size_t)b * ML + m0) * DM; Ah = Mh + o; Al = Ml + o; }
    else        { size_t o = ((size_t)b * QL + (m0 - ML)) * DM; Ah = Hh + o; Al = Hl + o; }
    size_t bo = (size_t)blockIdx.x * 128 * DM;
    float* Cp = C + ((size_t)b * KL + m0) * DM + blockIdx.x * 128;
    gemm2_core<128, false>(Ah, Al, DM, Bp + bo, DM, Cp, DM, DM);
}

// ============= score kernel: Q split x B plain fp16, K=64, 2-combo =======
__global__ __launch_bounds__(256)
void k_score2(const __half* __restrict__ Qh, const __half* __restrict__ Ql,
              const __half* __restrict__ Bp, float* __restrict__ Sout, int kBat)
{
    __shared__ __align__(1024) uint8_t sA[32768];
    __shared__ __align__(1024) uint8_t sB[16384];

    const int tid  = threadIdx.x;
    const int wid  = tid >> 5;
    const int lane = tid & 31;
    const int wm   = wid & 3;
    const int wn   = wid >> 2;

    const int z = blockIdx.z, b = z >> 4, h = z & 15;
    const int i0 = blockIdx.y * 128, j0 = blockIdx.x * 128;
    const int hoff = h * DH;

    const uint32_t a32 = smem_u32(sA), b32 = smem_u32(sB);

    {
        const size_t abase = ((size_t)(b * QL + i0)) * DM + hoff;
#pragma unroll
        for (int i = 0; i < 8; i++){
            int s = tid + (i << 8);
            int pg = s >> 10, rem = s & 1023, row = rem >> 3, j = rem & 7;
            const __half* src = (j < 4)
                ? Qh + abase + (size_t)row * DM + pg * 32 + j * 8
                : Ql + abase + (size_t)row * DM + pg * 32 + (j - 4) * 8;
            uint32_t off = (uint32_t)(pg * 16384) + SWZ((uint32_t)(row << 7) + (uint32_t)(j << 4));
            *reinterpret_cast<uint4*>(sA + off) = *reinterpret_cast<const uint4*>(src);
        }
    }
    {
        const size_t bbase = kBat ? ((size_t)(b * KL + j0)) * DM + hoff
                                  : (size_t)j0 * DM + hoff;
#pragma unroll
        for (int i = 0; i < 4; i++){
            int s = tid + (i << 8);
            int row = s >> 3, j = s & 7;
            const __half* src = Bp + bbase + (size_t)row * DM + j * 8;
            uint32_t off = SWZ((uint32_t)(row << 7) + (uint32_t)(j << 4));
            *reinterpret_cast<uint4*>(sB + off) = *reinterpret_cast<const uint4*>(src);
        }
    }
    __syncthreads();

    float acc[2][8][4];
#pragma unroll
    for (int mt = 0; mt < 2; mt++)
#pragma unroll
        for (int nt = 0; nt < 8; nt++)
#pragma unroll
            for (int q = 0; q < 4; q++) acc[mt][nt][q] = 0.0f;

    const uint32_t aRowOff0 = (uint32_t)((wm * 32 + (lane & 15)) << 7) + ((lane >> 4) << 4);
    const uint32_t bRowOff  = (uint32_t)((wn * 64 + (lane & 7)) << 7) + (((lane >> 3) & 1) << 4);

#pragma unroll
    for (int s16 = 0; s16 < 4; s16++){
        const uint32_t apg = (uint32_t)(s16 >> 1) * 16384u;
        const uint32_t hiOff = (uint32_t)((s16 & 1) << 5);
        const uint32_t bOff  = (uint32_t)(s16 << 5);

        uint32_t ah[2][4], al[2][4];
#pragma unroll
        for (int mt = 0; mt < 2; mt++){
            uint32_t base = aRowOff0 + (uint32_t)(mt << 11);
            ldsm_x4(ah[mt][0], ah[mt][1], ah[mt][2], ah[mt][3],
                    a32 + apg + SWZ(base + hiOff));
            ldsm_x4(al[mt][0], al[mt][1], al[mt][2], al[mt][3],
                    a32 + apg + SWZ(base + hiOff + 64));
        }
#pragma unroll
        for (int nt = 0; nt < 8; nt++){
            uint32_t bb[2];
            ldsm_x2(bb[0], bb[1], b32 + SWZ(bRowOff + (uint32_t)(nt << 10) + bOff));
            mma16816(acc[0][nt], ah[0], bb);
            mma16816(acc[1][nt], ah[1], bb);
            mma16816(acc[0][nt], al[0], bb);
            mma16816(acc[1][nt], al[1], bb);
        }
    }

    float* Cp = Sout + ((size_t)z * QL + i0) * KL + j0;
    const int r0 = wm * 32 + (lane >> 2);
    const int cc = (lane & 3) * 2;
#pragma unroll
    for (int mt = 0; mt < 2; mt++){
#pragma unroll
        for (int nt = 0; nt < 8; nt++){
            const int col = wn * 64 + nt * 8 + cc;
            float* p0 = Cp + (size_t)(r0 + mt * 16) * KL + col;
            float* p1 = Cp + (size_t)(r0 + mt * 16 + 8) * KL + col;
            *reinterpret_cast<float2*>(p0) = make_float2(acc[mt][nt][0], acc[mt][nt][1]);
            *reinterpret_cast<float2*>(p1) = make_float2(acc[mt][nt][2], acc[mt][nt][3]);
        }
    }
}

// ============= av kernel: P plain fp16 x VT split, 2-combo, K=2048 =======
__global__ __launch_bounds__(256)
void k_av2(const __half* __restrict__ P, const __half* __restrict__ VTh,
           const __half* __restrict__ VTl, float* __restrict__ AV)
{
    __shared__ __align__(1024) uint8_t sA[16384];
    __shared__ __align__(1024) uint8_t sB[16384];

    const int tid  = threadIdx.x;
    const int wid  = tid >> 5;
    const int lane = tid & 31;
    const int wm   = wid & 3;
    const int wn   = wid >> 2;

    const int z = blockIdx.z, b = z >> 4, h = z & 15;
    const int i0 = blockIdx.y * 128;
    const size_t prow = (size_t)z * QL + i0;
    const size_t vrow = (size_t)b * DM + h * DH;

    const uint32_t a32 = smem_u32(sA), b32 = smem_u32(sB);

    float acc[2][4][4];
#pragma unroll
    for (int mt = 0; mt < 2; mt++)
#pragma unroll
        for (int nt = 0; nt < 4; nt++)
#pragma unroll
            for (int q = 0; q < 4; q++) acc[mt][nt][q] = 0.0f;

    uint4 pa[4], pb[4];
    auto ldg_chunk = [&](int k0){
#pragma unroll
        for (int i = 0; i < 4; i++){
            int s = tid + (i << 8); int row = s >> 3, j = s & 7;
            pa[i] = *reinterpret_cast<const uint4*>(P + (prow + row) * KL + k0 + j * 8);
        }
#pragma unroll
        for (int i = 0; i < 4; i++){
            int s = tid + (i << 8);
            int pg = s >> 9, rem = s & 511, row = rem >> 3, j = rem & 7;
            const __half* src = (j < 4)
                ? VTh + (vrow + row) * KL + k0 + pg * 32 + j * 8
                : VTl + (vrow + row) * KL + k0 + pg * 32 + (j - 4) * 8;
            pb[i] = *reinterpret_cast<const uint4*>(src);
        }
    };

    const uint32_t aRowOff0 = (uint32_t)((wm * 32 + (lane & 15)) << 7) + ((lane >> 4) << 4);
    const uint32_t bRowOff  = (uint32_t)((wn * 32 + (lane & 7)) << 7) + (((lane >> 3) & 1) << 4);

    ldg_chunk(0);

    for (int c = 0; c < KL / 64; c++){
#pragma unroll
        for (int i = 0; i < 4; i++){
            int s = tid + (i << 8);
            uint32_t off = SWZ((uint32_t)((s >> 3) << 7) + (uint32_t)((s & 7) << 4));
            *reinterpret_cast<uint4*>(sA + off) = pa[i];
        }
#pragma unroll
        for (int i = 0; i < 4; i++){
            int s = tid + (i << 8);
            int pg = s >> 9, rem = s & 511;
            uint32_t off = (uint32_t)(pg * 8192)
                         + SWZ((uint32_t)((rem >> 3) << 7) + (uint32_t)((rem & 7) << 4));
            *reinterpret_cast<uint4*>(sB + off) = pb[i];
        }
        __syncthreads();

        if (c + 1 < KL / 64) ldg_chunk((c + 1) << 6);

#pragma unroll
        for (int s16 = 0; s16 < 4; s16++){
            const uint32_t aOff  = (uint32_t)(s16 << 5);
            const uint32_t bpg   = (uint32_t)(s16 >> 1) * 8192u;
            const uint32_t hiOff = (uint32_t)((s16 & 1) << 5);

            uint32_t av[2][4];
#pragma unroll
            for (int mt = 0; mt < 2; mt++){
                uint32_t base = aRowOff0 + (uint32_t)(mt << 11);
                ldsm_x4(av[mt][0], av[mt][1], av[mt][2], av[mt][3],
                        a32 + SWZ(base + aOff));
            }
#pragma unroll
            for (int nt = 0; nt < 4; nt++){
                uint32_t bh[2], bl[2];
                ldsm_x2(bh[0], bh[1], b32 + bpg + SWZ(bRowOff + (uint32_t)(nt << 10) + hiOff));
                mma16816(acc[0][nt], av[0], bh);
                mma16816(acc[1][nt], av[1], bh);
                ldsm_x2(bl[0], bl[1], b32 + bpg + SWZ(bRowOff + (uint32_t)(nt << 10) + hiOff + 64));
                mma16816(acc[0][nt], av[0], bl);
                mma16816(acc[1][nt], av[1], bl);
            }
        }
        __syncthreads();
    }

    float* Cp = AV + ((size_t)(b * QL + i0)) * DM + h * DH;
    const int r0 = wm * 32 + (lane >> 2);
    const int cc = (lane & 3) * 2;
#pragma unroll
    for (int mt = 0; mt < 2; mt++){
#pragma unroll
        for (int nt = 0; nt < 4; nt++){
            const int col = wn * 32 + nt * 8 + cc;
            float* p0 = Cp + (size_t)(r0 + mt * 16) * DM + col;
            float* p1 = Cp + (size_t)(r0 + mt * 16 + 8) * DM + col;
            *reinterpret_cast<float2*>(p0) = make_float2(acc[mt][nt][0], acc[mt][nt][1]);
            *reinterpret_cast<float2*>(p1) = make_float2(acc[mt][nt][2], acc[mt][nt][3]);
        }
    }
}

// ============================ conversions =================================
__device__ __forceinline__ void split1(float x, __half& h, __half& l){
    h = __float2half(x);
    l = __float2half(x - __half2float(h));
}

__global__ __launch_bounds__(256)
void k_split(const float* __restrict__ x, __half* __restrict__ h,
             __half* __restrict__ l, size_t n)
{
    size_t i = ((size_t)blockIdx.x * 256 + threadIdx.x) * 4;
    if (i >= n) return;
    float4 v = *reinterpret_cast<const float4*>(x + i);
    __half h0, h1, h2, h3, l0, l1, l2, l3;
    split1(v.x, h0, l0); split1(v.y, h1, l1);
    split1(v.z, h2, l2); split1(v.w, h3, l3);
    *reinterpret_cast<__half2*>(h + i)     = __halves2half2(h0, h1);
    *reinterpret_cast<__half2*>(h + i + 2) = __halves2half2(h2, h3);
    *reinterpret_cast<__half2*>(l + i)     = __halves2half2(l0, l1);
    *reinterpret_cast<__half2*>(l + i + 2) = __halves2half2(l2, l3);
}

__global__ __launch_bounds__(256)
void k_split_qbias(const float* __restrict__ q,
                   const float* __restrict__ b1, const float* __restrict__ b2,
                   __half* __restrict__ h1, __half* __restrict__ l1,
                   __half* __restrict__ h2, __half* __restrict__ l2,
                   size_t n)
{
    size_t i = ((size_t)blockIdx.x * 256 + threadIdx.x) * 4;
    if (i >= n) return;
    const int col = (int)(i & (DM - 1));
    float4 v = *reinterpret_cast<const float4*>(q + i);
    float4 a = *reinterpret_cast<const float4*>(b1 + col);
    float4 c = *reinterpret_cast<const float4*>(b2 + col);
    __half h0, h1b, h2b, h3, l0, l1b, l2b, l3;
    split1(v.x + a.x, h0, l0);  split1(v.y + a.y, h1b, l1b);
    split1(v.z + a.z, h2b, l2b); split1(v.w + a.w, h3, l3);
    *reinterpret_cast<__half2*>(h1 + i)     = __halves2half2(h0, h1b);
    *reinterpret_cast<__half2*>(h1 + i + 2) = __halves2half2(h2b, h3);
    *reinterpret_cast<__half2*>(l1 + i)     = __halves2half2(l0, l1b);
    *reinterpret_cast<__half2*>(l1 + i + 2) = __halves2half2(l2b, l3);
    split1(v.x + c.x, h0, l0);  split1(v.y + c.y, h1b, l1b);
    split1(v.z + c.z, h2b, l2b); split1(v.w + c.w, h3, l3);
    *reinterpret_cast<__half2*>(h2 + i)     = __halves2half2(h0, h1b);
    *reinterpret_cast<__half2*>(h2 + i + 2) = __halves2half2(h2b, h3);
    *reinterpret_cast<__half2*>(l2 + i)     = __halves2half2(l0, l1b);
    *reinterpret_cast<__half2*>(l2 + i + 2) = __halves2half2(l2b, l3);
}

// out[b][c][r] = split(x[b][r][c]) ; grid (C/32, R/32, batch), block (32,8)
__global__ __launch_bounds__(256)
void k_tsplit(const float* __restrict__ x, __half* __restrict__ th,
              __half* __restrict__ tl, int R, int C)
{
    __shared__ float t[32][33];
    const int bz = blockIdx.z;
    const float* xb = x + (size_t)bz * R * C;
    __half* ph = th + (size_t)bz * R * C;
    __half* pl = tl + (size_t)bz * R * C;
    const int c0 = blockIdx.x * 32, r0 = blockIdx.y * 32;
    const int tx = threadIdx.x, ty = threadIdx.y;
    for (int i = ty; i < 32; i += 8)
        t[i][tx] = xb[(size_t)(r0 + i) * C + c0 + tx];
    __syncthreads();
    for (int i = ty; i < 32; i += 8){
        __half h, l; split1(t[tx][i], h, l);
        ph[(size_t)(c0 + i) * R + r0 + tx] = h;
        pl[(size_t)(c0 + i) * R + r0 + tx] = l;
    }
}

// ============================ softmax =====================================
__global__ __launch_bounds__(256)
void k_softmax(const float* __restrict__ S, const float* __restrict__ BD,
               __half* __restrict__ Pp)
{
    const int row = blockIdx.x;
    const int i   = row & (QL - 1);
    const float* srow = S + (size_t)row * KL;
    const float* x0 = BD + (size_t)row * KL;
    const float* x1 = x0 + KL;

    const int tid = threadIdx.x, lane = tid & 31, warp = tid >> 5;
    __shared__ float red[8];

    float sc[8];
    float mx = -1e30f;
#pragma unroll
    for (int c = 0; c < 8; c++){
        const int j = c * 256 + tid;
        const int d = j - i;
        float bdv;
        if (d <= QL)           bdv = x0[j - i + (QL - 1)];
        else if (d == QL + 1)  bdv = 0.0f;
        else                   bdv = x1[j - i - (QL + 2)];
        const float v = (srow[j] + bdv) * 0.125f;
        sc[c] = v;
        mx = fmaxf(mx, v);
    }
#pragma unroll
    for (int o = 16; o > 0; o >>= 1) mx = fmaxf(mx, __shfl_xor_sync(0xffffffffu, mx, o));
    if (lane == 0) red[warp] = mx;
    __syncthreads();
    float rowmax = red[0];
#pragma unroll
    for (int w = 1; w < 8; w++) rowmax = fmaxf(rowmax, red[w]);
    __syncthreads();

    float sum = 0.0f;
#pragma unroll
    for (int c = 0; c < 8; c++){ sc[c] = __expf(sc[c] - rowmax); sum += sc[c]; }
#pragma unroll
    for (int o = 16; o > 0; o >>= 1) sum += __shfl_xor_sync(0xffffffffu, sum, o);
    if (lane == 0) red[warp] = sum;
    __syncthreads();
    float rowsum = 0.0f;
#pragma unroll
    for (int w = 0; w < 8; w++) rowsum += red[w];
    const float inv = 1.0f / rowsum;

    __half* ph = Pp + (size_t)row * KL;
#pragma unroll
    for (int c = 0; c < 8; c++){
        const int j = c * 256 + tid;
        ph[j] = __float2half(sc[c] * inv);
    }
}

// ============================ launch ======================================
extern "C" void kernel_launch(void* const* d_in, const int* in_sizes, int n_in,
                              void* d_out, int out_size)
{
    const float* h_in  = (const float*)d_in[0];
    const float* mem_p = (const float*)d_in[1];
    const float* r_p   = (const float*)d_in[2];
    const float* W[5]  = { (const float*)d_in[3], (const float*)d_in[4],
                           (const float*)d_in[5], (const float*)d_in[6],
                           (const float*)d_in[7] };   // Wq, Wk, Wv, Wr, Wo
    const float* rwb   = (const float*)d_in[8];
    const float* rrb   = (const float*)d_in[9];
    float* out = (float*)d_out;

    __half* hf; float* fp;
    cudaGetSymbolAddress((void**)&hf, g_hf);
    cudaGetSymbolAddress((void**)&fp, g_f);

    // 1) split inputs (fp16)
    k_split<<<2048, 256>>>(h_in,  hf + oHSPh, hf + oHSPl, SZ_2M);
    k_split<<<2048, 256>>>(mem_p, hf + oMSPh, hf + oMSPl, SZ_2M);
    k_split<<<2048, 256>>>(r_p,   hf + oRSPh, hf + oRSPl, SZ_2M);

    // 2) transpose+split weights: Wt[n][k] (hi = plain fp16 for 2-combo use)
    for (int w = 0; w < 5; w++){
        __half* th = hf + oWT + (size_t)w * 2 * SZ_1M;
        k_tsplit<<<dim3(32, 32, 1), dim3(32, 8)>>>(W[w], th, th + SZ_1M, 1024, 1024);
    }
    const __half *wq = hf + oWT,            *wk = hf + oWT + 2 * SZ_1M,
                 *wv = hf + oWT + 4 * SZ_1M, *wr = hf + oWT + 6 * SZ_1M,
                 *wo = hf + oWT + 8 * SZ_1M;

    // 3) projections
    k_proj<<<dim3(8, 16), 256>>>(hf + oHSPh, hf + oHSPl, wq, wq + SZ_1M, fp + fQ); // Q: 3-combo
    k_projcat2_f16<<<dim3(8, 16, 2), 256>>>(hf + oMSPh, hf + oMSPl,
                                            hf + oHSPh, hf + oHSPl, wk, hf + oKp); // K: fp16 direct
    k_projcat2_f32<<<dim3(8, 16, 2), 256>>>(hf + oMSPh, hf + oMSPl,
                                            hf + oHSPh, hf + oHSPl, wv, fp + fV);  // V
    k_proj2_f16<<<dim3(8, 16), 256>>>(hf + oRSPh, hf + oRSPl, wr, hf + oRHp);      // R: fp16 direct

    // 4) post-proj conversions
    k_split_qbias<<<2048, 256>>>(fp + fQ, rwb, rrb,
                                 hf + oQWh, hf + oQWl, hf + oQRh, hf + oQRl, SZ_2M);
    k_tsplit<<<dim3(32, 64, 2), dim3(32, 8)>>>(fp + fV, hf + oVTh, hf + oVTl, KL, DM);

    // 5) scores: 2-combo fp16 (Q split x plain B)
    k_score2<<<dim3(16, 8, 32), 256>>>(hf + oQWh, hf + oQWl, hf + oKp,  fp + fS, 1);
    k_score2<<<dim3(16, 8, 32), 256>>>(hf + oQRh, hf + oQRl, hf + oRHp, fp + fBD, 0);

    // 6) fused rel_shift + softmax -> plain fp16 probs
    k_softmax<<<B_SZ * NH * QL, 256>>>(fp + fS, fp + fBD, hf + oPp);

    // 7) attn_vec = prob @ v (2-combo: P plain x V split)
    k_av2<<<dim3(1, 8, 32), 256>>>(hf + oPp, hf + oVTh, hf + oVTl, fp + fAV);

    // 8) out = attn_vec @ Wo (2-combo)
    k_split<<<2048, 256>>>(fp + fAV, hf + oAVh, hf + oAVl, SZ_2M);
    k_proj2_f32<<<dim3(8, 16), 256>>>(hf + oAVh, hf + oAVl, wo, out);
}

// round 11
// speedup vs baseline: 3.2559x; 1.0584x over previous
#include <cuda_runtime.h>
#include <cuda_fp16.h>
#include <cstdint>
#include <cstddef>

#define B_SZ 2
#define QL   1024
#define ML   1024
#define KL   2048
#define DM   1024
#define NH   16
#define DH   64

// ============================ helpers =====================================
__device__ __forceinline__ uint32_t smem_u32(const void* p){
    uint32_t a;
    asm("{ .reg .u64 t; cvta.to.shared.u64 t, %1; cvt.u32.u64 %0, t; }" : "=r"(a) : "l"(p));
    return a;
}

#define SWZ(o) ((o) ^ (((o) >> 3) & 0x70))

__device__ __forceinline__ void ldsm_x4(uint32_t& r0, uint32_t& r1, uint32_t& r2,
                                        uint32_t& r3, uint32_t a){
    asm volatile("ldmatrix.sync.aligned.m8n8.x4.shared.b16 {%0,%1,%2,%3},[%4];"
                 : "=r"(r0), "=r"(r1), "=r"(r2), "=r"(r3) : "r"(a));
}
__device__ __forceinline__ void ldsm_x2(uint32_t& r0, uint32_t& r1, uint32_t a){
    asm volatile("ldmatrix.sync.aligned.m8n8.x2.shared.b16 {%0,%1},[%2];"
                 : "=r"(r0), "=r"(r1) : "r"(a));
}
__device__ __forceinline__ void ldsm_x2t(uint32_t& r0, uint32_t& r1, uint32_t a){
    asm volatile("ldmatrix.sync.aligned.m8n8.x2.trans.shared.b16 {%0,%1},[%2];"
                 : "=r"(r0), "=r"(r1) : "r"(a));
}
// fp16 MMA, fp32 accumulate
__device__ __forceinline__ void mma16816(float* c, const uint32_t* a, const uint32_t* b){
    asm volatile(
        "mma.sync.aligned.m16n8k16.row.col.f32.f16.f16.f32 "
        "{%0,%1,%2,%3},{%4,%5,%6,%7},{%8,%9},{%0,%1,%2,%3};"
        : "+f"(c[0]), "+f"(c[1]), "+f"(c[2]), "+f"(c[3])
        : "r"(a[0]), "r"(a[1]), "r"(a[2]), "r"(a[3]), "r"(b[0]), "r"(b[1]));
}

// ============================ scratch pools ===============================
#define SZ_1M ((size_t)1024 * 1024)
#define SZ_2M ((size_t)2048 * 1024)
#define SZ_4M ((size_t)4096 * 1024)
#define SZ_P  ((size_t)B_SZ * NH * QL * KL)

constexpr size_t oHSPh = 0,               oHSPl = oHSPh + SZ_2M;
constexpr size_t oMSPh = oHSPl + SZ_2M,   oMSPl = oMSPh + SZ_2M;
constexpr size_t oRSPh = oMSPl + SZ_2M,   oRSPl = oRSPh + SZ_2M;
constexpr size_t oWT   = oRSPl + SZ_2M;                       // 5 x (hi 1M | lo 1M)
constexpr size_t oQWh  = oWT + 10 * SZ_1M, oQWl = oQWh + SZ_2M;
constexpr size_t oQRh  = oQWl + SZ_2M,    oQRl = oQRh + SZ_2M;
constexpr size_t oKp   = oQRl + SZ_2M;                        // K plain fp16 (4M)
constexpr size_t oRHp  = oKp + SZ_4M;                         // R plain fp16 (2M)
constexpr size_t oVp   = oRHp + SZ_2M;                        // V plain fp16 [tok][feat] (4M)
constexpr size_t oPp   = oVp + SZ_4M;                         // P plain fp16 (64M)
constexpr size_t oAVh  = oPp + SZ_P,      oAVl = oAVh + SZ_2M;
constexpr size_t HF_TOTAL = oAVl + SZ_2M;

constexpr size_t fQ  = 0;
constexpr size_t fAV = fQ + SZ_2M;
constexpr size_t fS  = fAV + SZ_2M;
constexpr size_t fBD = fS + SZ_P;
constexpr size_t F_TOTAL = fBD + SZ_P;

__device__ __half g_hf[HF_TOTAL];
__device__ float  g_f [F_TOTAL];

// ============================ GEMM core (3-combo, split x split) ==========
// Used only for the Q projection (accuracy anchor).
template <int NT>
__device__ __forceinline__ void gemm_core(
    const __half* __restrict__ Ahi, const __half* __restrict__ Alo, int lda,
    const __half* __restrict__ Bhi, const __half* __restrict__ Blo, int ldb,
    float* __restrict__ C, int ldc, int K)
{
    __shared__ __align__(1024) uint8_t sA[128 * 128];
    __shared__ __align__(1024) uint8_t sB[NT * 128];

    const int tid  = threadIdx.x;
    const int wid  = tid >> 5;
    const int lane = tid & 31;
    const int wm   = wid & 3;
    const int wn   = wid >> 2;
    constexpr int WN     = NT / 2;
    constexpr int NTILES = WN / 8;
    constexpr int BSEG   = NT / 32;

    const uint32_t a32 = smem_u32(sA), b32 = smem_u32(sB);

    float acc[2][NTILES][4];
#pragma unroll
    for (int mt = 0; mt < 2; mt++)
#pragma unroll
        for (int nt = 0; nt < NTILES; nt++)
#pragma unroll
            for (int q = 0; q < 4; q++) acc[mt][nt][q] = 0.0f;

    uint4 pa[4], pb[BSEG];
    const int nch = K >> 5;

    auto ldg_chunk = [&](int k0){
#pragma unroll
        for (int i = 0; i < 4; i++){
            int s = tid + (i << 8); int row = s >> 3, j = s & 7;
            const __half* p = (j < 4)
                ? Ahi + (size_t)row * lda + k0 + j * 8
                : Alo + (size_t)row * lda + k0 + (j - 4) * 8;
            pa[i] = *reinterpret_cast<const uint4*>(p);
        }
#pragma unroll
        for (int i = 0; i < BSEG; i++){
            int s = tid + (i << 8); int row = s >> 3, j = s & 7;
            const __half* p = (j < 4)
                ? Bhi + (size_t)row * ldb + k0 + j * 8
                : Blo + (size_t)row * ldb + k0 + (j - 4) * 8;
            pb[i] = *reinterpret_cast<const uint4*>(p);
        }
    };

    const uint32_t aRowOff0 = (uint32_t)((wm * 32 + (lane & 15)) << 7) + ((lane >> 4) << 4);
    const uint32_t bRowOff  = (uint32_t)((wn * WN + (lane & 7)) << 7) + (((lane >> 3) & 1) << 4);

    ldg_chunk(0);

    for (int c = 0; c < nch; c++){
#pragma unroll
        for (int i = 0; i < 4; i++){
            int s = tid + (i << 8);
            uint32_t off = (uint32_t)((s >> 3) << 7) + (uint32_t)((s & 7) << 4);
            *reinterpret_cast<uint4*>(sA + SWZ(off)) = pa[i];
        }
#pragma unroll
        for (int i = 0; i < BSEG; i++){
            int s = tid + (i << 8);
            uint32_t off = (uint32_t)((s >> 3) << 7) + (uint32_t)((s & 7) << 4);
            *reinterpret_cast<uint4*>(sB + SWZ(off)) = pb[i];
        }
        __syncthreads();

        if (c + 1 < nch) ldg_chunk((c + 1) << 5);

#pragma unroll
        for (int kh = 0; kh < 2; kh++){
            const uint32_t hiOff = (uint32_t)(kh << 5);
            const uint32_t loOff = hiOff + 64;

            uint32_t ah[2][4], al[2][4];
#pragma unroll
            for (int mt = 0; mt < 2; mt++){
                uint32_t base = aRowOff0 + (uint32_t)(mt << 11);
                ldsm_x4(ah[mt][0], ah[mt][1], ah[mt][2], ah[mt][3],
                        a32 + SWZ(base + hiOff));
                ldsm_x4(al[mt][0], al[mt][1], al[mt][2], al[mt][3],
                        a32 + SWZ(base + loOff));
            }
#pragma unroll
            for (int nt = 0; nt < NTILES; nt++){
                uint32_t b[2];
                ldsm_x2(b[0], b[1], b32 + SWZ(bRowOff + (uint32_t)(nt << 10) + hiOff));
                mma16816(acc[0][nt], ah[0], b);
                mma16816(acc[1][nt], ah[1], b);
                mma16816(acc[0][nt], al[0], b);
                mma16816(acc[1][nt], al[1], b);
            }
#pragma unroll
            for (int nt = 0; nt < NTILES; nt++){
                uint32_t b[2];
                ldsm_x2(b[0], b[1], b32 + SWZ(bRowOff + (uint32_t)(nt << 10) + loOff));
                mma16816(acc[0][nt], ah[0], b);
                mma16816(acc[1][nt], ah[1], b);
            }
        }
        __syncthreads();
    }

    const int r0 = wm * 32 + (lane >> 2);
    const int cc = (lane & 3) * 2;
#pragma unroll
    for (int mt = 0; mt < 2; mt++){
#pragma unroll
        for (int nt = 0; nt < NTILES; nt++){
            const int col = wn * WN + nt * 8 + cc;
            float* p0 = C + (size_t)(r0 + mt * 16) * ldc + col;
            float* p1 = C + (size_t)(r0 + mt * 16 + 8) * ldc + col;
            *reinterpret_cast<float2*>(p0) = make_float2(acc[mt][nt][0], acc[mt][nt][1]);
            *reinterpret_cast<float2*>(p1) = make_float2(acc[mt][nt][2], acc[mt][nt][3]);
        }
    }
}

// ============================ GEMM core (2-combo, split x plain) ==========
template <int NT, bool OUT16>
__device__ __forceinline__ void gemm2_core(
    const __half* __restrict__ Ahi, const __half* __restrict__ Alo, int lda,
    const __half* __restrict__ Bp, int ldb,
    void* __restrict__ Cv, int ldc, int K)
{
    __shared__ __align__(1024) uint8_t sA[16384];
    __shared__ __align__(1024) uint8_t sB[2][NT * 128];

    const int tid  = threadIdx.x;
    const int wid  = tid >> 5;
    const int lane = tid & 31;
    const int wm   = wid & 3;
    const int wn   = wid >> 2;
    constexpr int WN     = NT / 2;
    constexpr int NTILES = WN / 8;
    constexpr int BSEG   = NT / 32;

    const uint32_t a32 = smem_u32(sA), b32 = smem_u32(&sB[0][0]);
    constexpr uint32_t BSTRIDE = (uint32_t)NT * 128;

    float acc[2][NTILES][4];
#pragma unroll
    for (int mt = 0; mt < 2; mt++)
#pragma unroll
        for (int nt = 0; nt < NTILES; nt++)
#pragma unroll
            for (int q = 0; q < 4; q++) acc[mt][nt][q] = 0.0f;

    uint4 pa[4], pb[BSEG];
    const int nch = K >> 5;

    auto ldgA = [&](int k0){
#pragma unroll
        for (int i = 0; i < 4; i++){
            int s = tid + (i << 8); int row = s >> 3, j = s & 7;
            const __half* p = (j < 4)
                ? Ahi + (size_t)row * lda + k0 + j * 8
                : Alo + (size_t)row * lda + k0 + (j - 4) * 8;
            pa[i] = *reinterpret_cast<const uint4*>(p);
        }
    };
    auto ldgB = [&](int k0){
#pragma unroll
        for (int i = 0; i < BSEG; i++){
            int s = tid + (i << 8); int row = s >> 3, j = s & 7;
            pb[i] = *reinterpret_cast<const uint4*>(Bp + (size_t)row * ldb + k0 + j * 8);
        }
    };

    const uint32_t aRowOff0 = (uint32_t)((wm * 32 + (lane & 15)) << 7) + ((lane >> 4) << 4);
    const uint32_t bRowOff  = (uint32_t)((wn * WN + (lane & 7)) << 7) + (((lane >> 3) & 1) << 4);

    ldgA(0);
    ldgB(0);

    for (int c = 0; c < nch; c++){
#pragma unroll
        for (int i = 0; i < 4; i++){
            int s = tid + (i << 8);
            uint32_t off = (uint32_t)((s >> 3) << 7) + (uint32_t)((s & 7) << 4);
            *reinterpret_cast<uint4*>(sA + SWZ(off)) = pa[i];
        }
        if ((c & 1) == 0){
            uint8_t* dst = &sB[(c >> 1) & 1][0];
#pragma unroll
            for (int i = 0; i < BSEG; i++){
                int s = tid + (i << 8);
                uint32_t off = (uint32_t)((s >> 3) << 7) + (uint32_t)((s & 7) << 4);
                *reinterpret_cast<uint4*>(dst + SWZ(off)) = pb[i];
            }
        }
        __syncthreads();

        if (c + 1 < nch) ldgA((c + 1) << 5);
        if ((c & 1) == 1){
            int nk0 = ((c >> 1) + 1) << 6;
            if (nk0 < K) ldgB(nk0);
        }

        const uint32_t bb = b32 + (uint32_t)((c >> 1) & 1) * BSTRIDE;
        const uint32_t bCol = (uint32_t)((c & 1) << 6);

#pragma unroll
        for (int kh = 0; kh < 2; kh++){
            const uint32_t hiOff = (uint32_t)(kh << 5);
            const uint32_t bOff  = bCol + hiOff;

            uint32_t ah[2][4], al[2][4];
#pragma unroll
            for (int mt = 0; mt < 2; mt++){
                uint32_t base = aRowOff0 + (uint32_t)(mt << 11);
                ldsm_x4(ah[mt][0], ah[mt][1], ah[mt][2], ah[mt][3],
                        a32 + SWZ(base + hiOff));
                ldsm_x4(al[mt][0], al[mt][1], al[mt][2], al[mt][3],
                        a32 + SWZ(base + hiOff + 64));
            }
#pragma unroll
            for (int nt = 0; nt < NTILES; nt++){
                uint32_t b[2];
                ldsm_x2(b[0], b[1], bb + SWZ(bRowOff + (uint32_t)(nt << 10) + bOff));
                mma16816(acc[0][nt], ah[0], b);
                mma16816(acc[1][nt], ah[1], b);
                mma16816(acc[0][nt], al[0], b);
                mma16816(acc[1][nt], al[1], b);
            }
        }
        __syncthreads();
    }

    const int r0 = wm * 32 + (lane >> 2);
    const int cc = (lane & 3) * 2;
    if (OUT16){
        __half* Ch = reinterpret_cast<__half*>(Cv);
#pragma unroll
        for (int mt = 0; mt < 2; mt++){
#pragma unroll
            for (int nt = 0; nt < NTILES; nt++){
                const int col = wn * WN + nt * 8 + cc;
                __half2 v0 = __floats2half2_rn(acc[mt][nt][0], acc[mt][nt][1]);
                __half2 v1 = __floats2half2_rn(acc[mt][nt][2], acc[mt][nt][3]);
                *reinterpret_cast<__half2*>(Ch + (size_t)(r0 + mt * 16) * ldc + col)     = v0;
                *reinterpret_cast<__half2*>(Ch + (size_t)(r0 + mt * 16 + 8) * ldc + col) = v1;
            }
        }
    } else {
        float* C = reinterpret_cast<float*>(Cv);
#pragma unroll
        for (int mt = 0; mt < 2; mt++){
#pragma unroll
            for (int nt = 0; nt < NTILES; nt++){
                const int col = wn * WN + nt * 8 + cc;
                float* p0 = C + (size_t)(r0 + mt * 16) * ldc + col;
                float* p1 = C + (size_t)(r0 + mt * 16 + 8) * ldc + col;
                *reinterpret_cast<float2*>(p0) = make_float2(acc[mt][nt][0], acc[mt][nt][1]);
                *reinterpret_cast<float2*>(p1) = make_float2(acc[mt][nt][2], acc[mt][nt][3]);
            }
        }
    }
}

// ============================ GEMM wrappers ===============================
__global__ __launch_bounds__(256)
void k_proj(const __half* __restrict__ Ah, const __half* __restrict__ Al,
            const __half* __restrict__ Bh, const __half* __restrict__ Bl,
            float* __restrict__ C)
{
    size_t ao = (size_t)blockIdx.y * 128 * DM;
    size_t bo = (size_t)blockIdx.x * 128 * DM;
    float* Cp = C + (size_t)blockIdx.y * 128 * DM + blockIdx.x * 128;
    gemm_core<128>(Ah + ao, Al + ao, DM, Bh + bo, Bl + bo, DM, Cp, DM, DM);
}

__global__ __launch_bounds__(256)
void k_proj2_f16(const __half* __restrict__ Ah, const __half* __restrict__ Al,
                 const __half* __restrict__ Bp, __half* __restrict__ C)
{
    size_t ao = (size_t)blockIdx.y * 128 * DM;
    size_t bo = (size_t)blockIdx.x * 128 * DM;
    __half* Cp = C + (size_t)blockIdx.y * 128 * DM + blockIdx.x * 128;
    gemm2_core<128, true>(Ah + ao, Al + ao, DM, Bp + bo, DM, Cp, DM, DM);
}

__global__ __launch_bounds__(256)
void k_proj2_f32(const __half* __restrict__ Ah, const __half* __restrict__ Al,
                 const __half* __restrict__ Bp, float* __restrict__ C)
{
    size_t ao = (size_t)blockIdx.y * 128 * DM;
    size_t bo = (size_t)blockIdx.x * 128 * DM;
    float* Cp = C + (size_t)blockIdx.y * 128 * DM + blockIdx.x * 128;
    gemm2_core<128, false>(Ah + ao, Al + ao, DM, Bp + bo, DM, Cp, DM, DM);
}

__global__ __launch_bounds__(256)
void k_projcat2_f16(const __half* __restrict__ Mh, const __half* __restrict__ Ml,
                    const __half* __restrict__ Hh, const __half* __restrict__ Hl,
                    const __half* __restrict__ Bp, __half* __restrict__ C)
{
    const int b = blockIdx.z, m0 = blockIdx.y * 128;
    const __half *Ah, *Al;
    if (m0 < ML){ size_t o = ((size_t)b * ML + m0) * DM; Ah = Mh + o; Al = Ml + o; }
    else        { size_t o = ((size_t)b * QL + (m0 - ML)) * DM; Ah = Hh + o; Al = Hl + o; }
    size_t bo = (size_t)blockIdx.x * 128 * DM;
    __half* Cp = C + ((size_t)b * KL + m0) * DM + blockIdx.x * 128;
    gemm2_core<128, true>(Ah, Al, DM, Bp + bo, DM, Cp, DM, DM);
}

// ============= score kernel: Q split x B plain fp16, K=64, 2-combo =======
__global__ __launch_bounds__(256)
void k_score2(const __half* __restrict__ Qh, const __half* __restrict__ Ql,
              const __half* __restrict__ Bp, float* __restrict__ Sout, int kBat)
{
    __shared__ __align__(1024) uint8_t sA[32768];
    __shared__ __align__(1024) uint8_t sB[16384];

    const int tid  = threadIdx.x;
    const int wid  = tid >> 5;
    const int lane = tid & 31;
    const int wm   = wid & 3;
    const int wn   = wid >> 2;

    const int z = blockIdx.z, b = z >> 4, h = z & 15;
    const int i0 = blockIdx.y * 128, j0 = blockIdx.x * 128;
    const int hoff = h * DH;

    const uint32_t a32 = smem_u32(sA), b32 = smem_u32(sB);

    {
        const size_t abase = ((size_t)(b * QL + i0)) * DM + hoff;
#pragma unroll
        for (int i = 0; i < 8; i++){
            int s = tid + (i << 8);
            int pg = s >> 10, rem = s & 1023, row = rem >> 3, j = rem & 7;
            const __half* src = (j < 4)
                ? Qh + abase + (size_t)row * DM + pg * 32 + j * 8
                : Ql + abase + (size_t)row * DM + pg * 32 + (j - 4) * 8;
            uint32_t off = (uint32_t)(pg * 16384) + SWZ((uint32_t)(row << 7) + (uint32_t)(j << 4));
            *reinterpret_cast<uint4*>(sA + off) = *reinterpret_cast<const uint4*>(src);
        }
    }
    {
        const size_t bbase = kBat ? ((size_t)(b * KL + j0)) * DM + hoff
                                  : (size_t)j0 * DM + hoff;
#pragma unroll
        for (int i = 0; i < 4; i++){
            int s = tid + (i << 8);
            int row = s >> 3, j = s & 7;
            const __half* src = Bp + bbase + (size_t)row * DM + j * 8;
            uint32_t off = SWZ((uint32_t)(row << 7) + (uint32_t)(j << 4));
            *reinterpret_cast<uint4*>(sB + off) = *reinterpret_cast<const uint4*>(src);
        }
    }
    __syncthreads();

    float acc[2][8][4];
#pragma unroll
    for (int mt = 0; mt < 2; mt++)
#pragma unroll
        for (int nt = 0; nt < 8; nt++)
#pragma unroll
            for (int q = 0; q < 4; q++) acc[mt][nt][q] = 0.0f;

    const uint32_t aRowOff0 = (uint32_t)((wm * 32 + (lane & 15)) << 7) + ((lane >> 4) << 4);
    const uint32_t bRowOff  = (uint32_t)((wn * 64 + (lane & 7)) << 7) + (((lane >> 3) & 1) << 4);

#pragma unroll
    for (int s16 = 0; s16 < 4; s16++){
        const uint32_t apg = (uint32_t)(s16 >> 1) * 16384u;
        const uint32_t hiOff = (uint32_t)((s16 & 1) << 5);
        const uint32_t bOff  = (uint32_t)(s16 << 5);

        uint32_t ah[2][4], al[2][4];
#pragma unroll
        for (int mt = 0; mt < 2; mt++){
            uint32_t base = aRowOff0 + (uint32_t)(mt << 11);
            ldsm_x4(ah[mt][0], ah[mt][1], ah[mt][2], ah[mt][3],
                    a32 + apg + SWZ(base + hiOff));
            ldsm_x4(al[mt][0], al[mt][1], al[mt][2], al[mt][3],
                    a32 + apg + SWZ(base + hiOff + 64));
        }
#pragma unroll
        for (int nt = 0; nt < 8; nt++){
            uint32_t bb[2];
            ldsm_x2(bb[0], bb[1], b32 + SWZ(bRowOff + (uint32_t)(nt << 10) + bOff));
            mma16816(acc[0][nt], ah[0], bb);
            mma16816(acc[1][nt], ah[1], bb);
            mma16816(acc[0][nt], al[0], bb);
            mma16816(acc[1][nt], al[1], bb);
        }
    }

    float* Cp = Sout + ((size_t)z * QL + i0) * KL + j0;
    const int r0 = wm * 32 + (lane >> 2);
    const int cc = (lane & 3) * 2;
#pragma unroll
    for (int mt = 0; mt < 2; mt++){
#pragma unroll
        for (int nt = 0; nt < 8; nt++){
            const int col = wn * 64 + nt * 8 + cc;
            float* p0 = Cp + (size_t)(r0 + mt * 16) * KL + col;
            float* p1 = Cp + (size_t)(r0 + mt * 16 + 8) * KL + col;
            *reinterpret_cast<float2*>(p0) = make_float2(acc[mt][nt][0], acc[mt][nt][1]);
            *reinterpret_cast<float2*>(p1) = make_float2(acc[mt][nt][2], acc[mt][nt][3]);
        }
    }
}

// ===== av kernel: P plain fp16 x V plain fp16 (trans-B), 1 combo =========
// A (P) smem: 128 rows x 128B (64 K per chunk). B (V) smem: 64 token rows x
// 128B (64 feats). B fragments via ldmatrix.trans from [tok][feat] layout.
__global__ __launch_bounds__(256)
void k_av3(const __half* __restrict__ P, const __half* __restrict__ Vp,
           float* __restrict__ AV)
{
    __shared__ __align__(1024) uint8_t sA[16384];
    __shared__ __align__(1024) uint8_t sB[8192];

    const int tid  = threadIdx.x;
    const int wid  = tid >> 5;
    const int lane = tid & 31;
    const int wm   = wid & 3;
    const int wn   = wid >> 2;

    const int z = blockIdx.z, b = z >> 4, h = z & 15;
    const int i0 = blockIdx.y * 128;
    const size_t prow = (size_t)z * QL + i0;
    const size_t vbase = (size_t)b * KL * DM + h * DH;   // V[b][tok][h*64..]

    const uint32_t a32 = smem_u32(sA), b32 = smem_u32(sB);

    float acc[2][4][4];
#pragma unroll
    for (int mt = 0; mt < 2; mt++)
#pragma unroll
        for (int nt = 0; nt < 4; nt++)
#pragma unroll
            for (int q = 0; q < 4; q++) acc[mt][nt][q] = 0.0f;

    uint4 pa[4], pb[2];
    auto ldg_chunk = [&](int k0){
#pragma unroll
        for (int i = 0; i < 4; i++){
            int s = tid + (i << 8); int row = s >> 3, j = s & 7;
            pa[i] = *reinterpret_cast<const uint4*>(P + (prow + row) * KL + k0 + j * 8);
        }
#pragma unroll
        for (int i = 0; i < 2; i++){
            int s = tid + (i << 8); int row = s >> 3, j = s & 7;   // row: token 0..63
            pb[i] = *reinterpret_cast<const uint4*>(Vp + vbase + (size_t)(k0 + row) * DM + j * 8);
        }
    };

    const uint32_t aRowOff0 = (uint32_t)((wm * 32 + (lane & 15)) << 7) + ((lane >> 4) << 4);
    const uint32_t n0byte   = (uint32_t)((wn * 32) << 1);   // warp n-offset in bytes

    ldg_chunk(0);

    for (int c = 0; c < KL / 64; c++){
#pragma unroll
        for (int i = 0; i < 4; i++){
            int s = tid + (i << 8);
            uint32_t off = SWZ((uint32_t)((s >> 3) << 7) + (uint32_t)((s & 7) << 4));
            *reinterpret_cast<uint4*>(sA + off) = pa[i];
        }
#pragma unroll
        for (int i = 0; i < 2; i++){
            int s = tid + (i << 8);
            uint32_t off = SWZ((uint32_t)((s >> 3) << 7) + (uint32_t)((s & 7) << 4));
            *reinterpret_cast<uint4*>(sB + off) = pb[i];
        }
        __syncthreads();

        if (c + 1 < KL / 64) ldg_chunk((c + 1) << 6);

#pragma unroll
        for (int s16 = 0; s16 < 4; s16++){
            const uint32_t aOff = (uint32_t)(s16 << 5);

            uint32_t av[2][4];
#pragma unroll
            for (int mt = 0; mt < 2; mt++){
                uint32_t base = aRowOff0 + (uint32_t)(mt << 11);
                ldsm_x4(av[mt][0], av[mt][1], av[mt][2], av[mt][3],
                        a32 + SWZ(base + aOff));
            }
            // trans-B: rows = tokens s16*16 + (lane&15), col byte = n0
            const uint32_t brow = (uint32_t)(((s16 << 4) + (lane & 15)) << 7);
#pragma unroll
            for (int nt = 0; nt < 4; nt++){
                uint32_t bb[2];
                ldsm_x2t(bb[0], bb[1], b32 + SWZ(brow + n0byte + (uint32_t)(nt << 4)));
                mma16816(acc[0][nt], av[0], bb);
                mma16816(acc[1][nt], av[1], bb);
            }
        }
        __syncthreads();
    }

    float* Cp = AV + ((size_t)(b * QL + i0)) * DM + h * DH;
    const int r0 = wm * 32 + (lane >> 2);
    const int cc = (lane & 3) * 2;
#pragma unroll
    for (int mt = 0; mt < 2; mt++){
#pragma unroll
        for (int nt = 0; nt < 4; nt++){
            const int col = wn * 32 + nt * 8 + cc;
            float* p0 = Cp + (size_t)(r0 + mt * 16) * DM + col;
            float* p1 = Cp + (size_t)(r0 + mt * 16 + 8) * DM + col;
            *reinterpret_cast<float2*>(p0) = make_float2(acc[mt][nt][0], acc[mt][nt][1]);
            *reinterpret_cast<float2*>(p1) = make_float2(acc[mt][nt][2], acc[mt][nt][3]);
        }
    }
}

// ============================ conversions =================================
__device__ __forceinline__ void split1(float x, __half& h, __half& l){
    h = __float2half(x);
    l = __float2half(x - __half2float(h));
}

__global__ __launch_bounds__(256)
void k_split(const float* __restrict__ x, __half* __restrict__ h,
             __half* __restrict__ l, size_t n)
{
    size_t i = ((size_t)blockIdx.x * 256 + threadIdx.x) * 4;
    if (i >= n) return;
    float4 v = *reinterpret_cast<const float4*>(x + i);
    __half h0, h1, h2, h3, l0, l1, l2, l3;
    split1(v.x, h0, l0); split1(v.y, h1, l1);
    split1(v.z, h2, l2); split1(v.w, h3, l3);
    *reinterpret_cast<__half2*>(h + i)     = __halves2half2(h0, h1);
    *reinterpret_cast<__half2*>(h + i + 2) = __halves2half2(h2, h3);
    *reinterpret_cast<__half2*>(l + i)     = __halves2half2(l0, l1);
    *reinterpret_cast<__half2*>(l + i + 2) = __halves2half2(l2, l3);
}

__global__ __launch_bounds__(256)
void k_split_qbias(const float* __restrict__ q,
                   const float* __restrict__ b1, const float* __restrict__ b2,
                   __half* __restrict__ h1, __half* __restrict__ l1,
                   __half* __restrict__ h2, __half* __restrict__ l2,
                   size_t n)
{
    size_t i = ((size_t)blockIdx.x * 256 + threadIdx.x) * 4;
    if (i >= n) return;
    const int col = (int)(i & (DM - 1));
    float4 v = *reinterpret_cast<const float4*>(q + i);
    float4 a = *reinterpret_cast<const float4*>(b1 + col);
    float4 c = *reinterpret_cast<const float4*>(b2 + col);
    __half h0, h1b, h2b, h3, l0, l1b, l2b, l3;
    split1(v.x + a.x, h0, l0);  split1(v.y + a.y, h1b, l1b);
    split1(v.z + a.z, h2b, l2b); split1(v.w + a.w, h3, l3);
    *reinterpret_cast<__half2*>(h1 + i)     = __halves2half2(h0, h1b);
    *reinterpret_cast<__half2*>(h1 + i + 2) = __halves2half2(h2b, h3);
    *reinterpret_cast<__half2*>(l1 + i)     = __halves2half2(l0, l1b);
    *reinterpret_cast<__half2*>(l1 + i + 2) = __halves2half2(l2b, l3);
    split1(v.x + c.x, h0, l0);  split1(v.y + c.y, h1b, l1b);
    split1(v.z + c.z, h2b, l2b); split1(v.w + c.w, h3, l3);
    *reinterpret_cast<__half2*>(h2 + i)     = __halves2half2(h0, h1b);
    *reinterpret_cast<__half2*>(h2 + i + 2) = __halves2half2(h2b, h3);
    *reinterpret_cast<__half2*>(l2 + i)     = __halves2half2(l0, l1b);
    *reinterpret_cast<__half2*>(l2 + i + 2) = __halves2half2(l2b, l3);
}

// out[b][c][r] = split(x[b][r][c]) ; grid (C/32, R/32, batch), block (32,8)
__global__ __launch_bounds__(256)
void k_tsplit(const float* __restrict__ x, __half* __restrict__ th,
              __half* __restrict__ tl, int R, int C)
{
    __shared__ float t[32][33];
    const int bz = blockIdx.z;
    const float* xb = x + (size_t)bz * R * C;
    __half* ph = th + (size_t)bz * R * C;
    __half* pl = tl + (size_t)bz * R * C;
    const int c0 = blockIdx.x * 32, r0 = blockIdx.y * 32;
    const int tx = threadIdx.x, ty = threadIdx.y;
    for (int i = ty; i < 32; i += 8)
        t[i][tx] = xb[(size_t)(r0 + i) * C + c0 + tx];
    __syncthreads();
    for (int i = ty; i < 32; i += 8){
        __half h, l; split1(t[tx][i], h, l);
        ph[(size_t)(c0 + i) * R + r0 + tx] = h;
        pl[(size_t)(c0 + i) * R + r0 + tx] = l;
    }
}

// ============================ softmax =====================================
__global__ __launch_bounds__(256)
void k_softmax(const float* __restrict__ S, const float* __restrict__ BD,
               __half* __restrict__ Pp)
{
    const int row = blockIdx.x;
    const int i   = row & (QL - 1);
    const float* srow = S + (size_t)row * KL;
    const float* x0 = BD + (size_t)row * KL;
    const float* x1 = x0 + KL;

    const int tid = threadIdx.x, lane = tid & 31, warp = tid >> 5;
    __shared__ float red[8];

    float sc[8];
    float mx = -1e30f;
#pragma unroll
    for (int c = 0; c < 8; c++){
        const int j = c * 256 + tid;
        const int d = j - i;
        float bdv;
        if (d <= QL)           bdv = x0[j - i + (QL - 1)];
        else if (d == QL + 1)  bdv = 0.0f;
        else                   bdv = x1[j - i - (QL + 2)];
        const float v = (srow[j] + bdv) * 0.125f;
        sc[c] = v;
        mx = fmaxf(mx, v);
    }
#pragma unroll
    for (int o = 16; o > 0; o >>= 1) mx = fmaxf(mx, __shfl_xor_sync(0xffffffffu, mx, o));
    if (lane == 0) red[warp] = mx;
    __syncthreads();
    float rowmax = red[0];
#pragma unroll
    for (int w = 1; w < 8; w++) rowmax = fmaxf(rowmax, red[w]);
    __syncthreads();

    float sum = 0.0f;
#pragma unroll
    for (int c = 0; c < 8; c++){ sc[c] = __expf(sc[c] - rowmax); sum += sc[c]; }
#pragma unroll
    for (int o = 16; o > 0; o >>= 1) sum += __shfl_xor_sync(0xffffffffu, sum, o);
    if (lane == 0) red[warp] = sum;
    __syncthreads();
    float rowsum = 0.0f;
#pragma unroll
    for (int w = 0; w < 8; w++) rowsum += red[w];
    const float inv = 1.0f / rowsum;

    __half* ph = Pp + (size_t)row * KL;
#pragma unroll
    for (int c = 0; c < 8; c++){
        const int j = c * 256 + tid;
        ph[j] = __float2half(sc[c] * inv);
    }
}

// ============================ launch ======================================
extern "C" void kernel_launch(void* const* d_in, const int* in_sizes, int n_in,
                              void* d_out, int out_size)
{
    const float* h_in  = (const float*)d_in[0];
    const float* mem_p = (const float*)d_in[1];
    const float* r_p   = (const float*)d_in[2];
    const float* W[5]  = { (const float*)d_in[3], (const float*)d_in[4],
                           (const float*)d_in[5], (const float*)d_in[6],
                           (const float*)d_in[7] };   // Wq, Wk, Wv, Wr, Wo
    const float* rwb   = (const float*)d_in[8];
    const float* rrb   = (const float*)d_in[9];
    float* out = (float*)d_out;

    __half* hf; float* fp;
    cudaGetSymbolAddress((void**)&hf, g_hf);
    cudaGetSymbolAddress((void**)&fp, g_f);

    // 1) split inputs (fp16)
    k_split<<<2048, 256>>>(h_in,  hf + oHSPh, hf + oHSPl, SZ_2M);
    k_split<<<2048, 256>>>(mem_p, hf + oMSPh, hf + oMSPl, SZ_2M);
    k_split<<<2048, 256>>>(r_p,   hf + oRSPh, hf + oRSPl, SZ_2M);

    // 2) transpose+split weights: Wt[n][k] (hi = plain fp16 for 2-combo use)
    for (int w = 0; w < 5; w++){
        __half* th = hf + oWT + (size_t)w * 2 * SZ_1M;
        k_tsplit<<<dim3(32, 32, 1), dim3(32, 8)>>>(W[w], th, th + SZ_1M, 1024, 1024);
    }
    const __half *wq = hf + oWT,            *wk = hf + oWT + 2 * SZ_1M,
                 *wv = hf + oWT + 4 * SZ_1M, *wr = hf + oWT + 6 * SZ_1M,
                 *wo = hf + oWT + 8 * SZ_1M;

    // 3) projections
    k_proj<<<dim3(8, 16), 256>>>(hf + oHSPh, hf + oHSPl, wq, wq + SZ_1M, fp + fQ); // Q: 3-combo
    k_projcat2_f16<<<dim3(8, 16, 2), 256>>>(hf + oMSPh, hf + oMSPl,
                                            hf + oHSPh, hf + oHSPl, wk, hf + oKp); // K: fp16 direct
    k_projcat2_f16<<<dim3(8, 16, 2), 256>>>(hf + oMSPh, hf + oMSPl,
                                            hf + oHSPh, hf + oHSPl, wv, hf + oVp); // V: fp16 direct
    k_proj2_f16<<<dim3(8, 16), 256>>>(hf + oRSPh, hf + oRSPl, wr, hf + oRHp);      // R: fp16 direct

    // 4) post-proj conversions (Q only)
    k_split_qbias<<<2048, 256>>>(fp + fQ, rwb, rrb,
                                 hf + oQWh, hf + oQWl, hf + oQRh, hf + oQRl, SZ_2M);

    // 5) scores: 2-combo fp16 (Q split x plain B)
    k_score2<<<dim3(16, 8, 32), 256>>>(hf + oQWh, hf + oQWl, hf + oKp,  fp + fS, 1);
    k_score2<<<dim3(16, 8, 32), 256>>>(hf + oQRh, hf + oQRl, hf + oRHp, fp + fBD, 0);

    // 6) fused rel_shift + softmax -> plain fp16 probs
    k_softmax<<<B_SZ * NH * QL, 256>>>(fp + fS, fp + fBD, hf + oPp);

    // 7) attn_vec = prob @ v (1-combo: P plain x V plain, trans-B)
    k_av3<<<dim3(1, 8, 32), 256>>>(hf + oPp, hf + oVp, fp + fAV);

    // 8) out = attn_vec @ Wo (2-combo)
    k_split<<<2048, 256>>>(fp + fAV, hf + oAVh, hf + oAVl, SZ_2M);
    k_proj2_f32<<<dim3(8, 16), 256>>>(hf + oAVh, hf + oAVl, wo, out);
}